// round 12
// baseline (speedup 1.0000x reference)
#include <cuda_runtime.h>
#include <cuda_bf16.h>
#include <math.h>
#include <stdint.h>

#define BB 8
#define SS 512
#define DD 768
#define HH 12
#define DH 64
#define LL 12
#define FFD 3072
#define MTOK (BB*SS)
#define NQKV 2304

// activations
__device__ __align__(256) float g_h  [MTOK*DD];
__device__ __align__(256) float g_t1 [MTOK*DD];
__device__ __align__(256) float g_t2 [MTOK*DD];
__device__ __align__(256) float g_t3 [MTOK*DD];
__device__ __align__(256) float g_ctx[MTOK*DD];
__device__ __align__(256) float g_ff [MTOK*FFD];
__device__ __align__(256) int8_t g_hq1[MTOK*DD];
__device__ __align__(256) int8_t g_hq2[MTOK*DD];
__device__ __align__(256) int8_t g_cq1[MTOK*DD];
__device__ __align__(256) int8_t g_cq2[MTOK*DD];
__device__ __align__(256) int8_t g_fq1[MTOK*FFD];
__device__ __align__(256) int8_t g_fq2[MTOK*FFD];
__device__ __align__(256) float g_hs[MTOK];
__device__ __align__(256) float g_cs[MTOK];
__device__ __align__(256) float g_fs[MTOK];
__device__ __align__(256) __nv_bfloat16 g_qkv_h[MTOK*NQKV];
__device__ __align__(256) __nv_bfloat16 g_qkv_l[MTOK*NQKV];

// weights: fp32 transposed, then int8 2-level
__device__ __align__(256) float g_WTq[LL*NQKV*DD];
__device__ __align__(256) float g_WTo[LL*DD*DD];
__device__ __align__(256) float g_WTi[LL*FFD*DD];
__device__ __align__(256) float g_WTf[LL*DD*FFD];
__device__ __align__(256) int8_t g_wq1_q[LL*NQKV*DD]; __device__ __align__(256) int8_t g_wq2_q[LL*NQKV*DD];
__device__ __align__(256) int8_t g_wq1_o[LL*DD*DD];   __device__ __align__(256) int8_t g_wq2_o[LL*DD*DD];
__device__ __align__(256) int8_t g_wq1_i[LL*FFD*DD];  __device__ __align__(256) int8_t g_wq2_i[LL*FFD*DD];
__device__ __align__(256) int8_t g_wq1_f[LL*DD*FFD];  __device__ __align__(256) int8_t g_wq2_f[LL*DD*FFD];
__device__ __align__(256) float g_ws_q[LL*NQKV];
__device__ __align__(256) float g_ws_o[LL*DD];
__device__ __align__(256) float g_ws_i[LL*FFD];
__device__ __align__(256) float g_ws_f[LL*DD];
__device__ __align__(256) float g_bqkv[LL*NQKV];

// ---------------- helpers ------------------------------------------------------
__device__ __forceinline__ uint32_t smem_u32(const void* p) {
    uint32_t a;
    asm("{ .reg .u64 t; cvta.to.shared.u64 t, %1; cvt.u32.u64 %0, t; }" : "=r"(a) : "l"(p));
    return a;
}
__device__ __forceinline__ uint32_t swz(uint32_t o) { return o ^ ((o >> 3) & 0x70); }
__device__ __forceinline__ void cpa16(uint32_t saddr, const void* g) {
    asm volatile("cp.async.cg.shared.global [%0], [%1], 16;" :: "r"(saddr), "l"(g));
}
__device__ __forceinline__ void cp_commit() {
    asm volatile("cp.async.commit_group;" ::: "memory");
}
template <int N>
__device__ __forceinline__ void cp_wait() {
    asm volatile("cp.async.wait_group %0;" :: "n"(N) : "memory");
}
__device__ __forceinline__ void ldsm4(uint32_t& r0, uint32_t& r1, uint32_t& r2, uint32_t& r3,
                                      uint32_t addr) {
    asm volatile("ldmatrix.sync.aligned.m8n8.x4.shared.b16 {%0,%1,%2,%3}, [%4];"
                 : "=r"(r0), "=r"(r1), "=r"(r2), "=r"(r3) : "r"(addr));
}
__device__ __forceinline__ void ldsm4t(uint32_t& r0, uint32_t& r1, uint32_t& r2, uint32_t& r3,
                                       uint32_t addr) {
    asm volatile("ldmatrix.sync.aligned.m8n8.x4.trans.shared.b16 {%0,%1,%2,%3}, [%4];"
                 : "=r"(r0), "=r"(r1), "=r"(r2), "=r"(r3) : "r"(addr));
}
__device__ __forceinline__ void mma_bf16(float* d, const uint32_t* a, const uint32_t* b) {
    asm volatile("mma.sync.aligned.m16n8k16.row.col.f32.bf16.bf16.f32 "
                 "{%0,%1,%2,%3}, {%4,%5,%6,%7}, {%8,%9}, {%0,%1,%2,%3};"
                 : "+f"(d[0]), "+f"(d[1]), "+f"(d[2]), "+f"(d[3])
                 : "r"(a[0]), "r"(a[1]), "r"(a[2]), "r"(a[3]), "r"(b[0]), "r"(b[1]));
}
__device__ __forceinline__ void mma_s8(int* d, const uint32_t* a, const uint32_t* b) {
    asm volatile("mma.sync.aligned.m16n8k32.row.col.s32.s8.s8.s32 "
                 "{%0,%1,%2,%3}, {%4,%5,%6,%7}, {%8,%9}, {%0,%1,%2,%3};"
                 : "+r"(d[0]), "+r"(d[1]), "+r"(d[2]), "+r"(d[3])
                 : "r"(a[0]), "r"(a[1]), "r"(a[2]), "r"(a[3]), "r"(b[0]), "r"(b[1]));
}
__device__ __forceinline__ void split_bf16(float x, __nv_bfloat16& hi, __nv_bfloat16& lo) {
    hi = __float2bfloat16(x);
    lo = __float2bfloat16(x - __bfloat162float(hi));
}
__device__ __forceinline__ void pack2(float a, float b, uint32_t& ph, uint32_t& pl) {
    __nv_bfloat16 ha, la, hb, lb;
    split_bf16(a, ha, la); split_bf16(b, hb, lb);
    __nv_bfloat162 th(ha, hb), tl(la, lb);
    ph = *(uint32_t*)&th; pl = *(uint32_t*)&tl;
}
__device__ __forceinline__ void quant2(float x, float inv, int8_t& q1, int8_t& q2) {
    float a = x * inv;
    float r1 = rintf(a);
    float r2 = fminf(fmaxf(rintf((a - r1) * 256.f), -127.f), 127.f);
    q1 = (int8_t)(int)r1; q2 = (int8_t)(int)r2;
}
__device__ __forceinline__ float blockReduceSum(float v, float* red) {
    int lane = threadIdx.x & 31, w = threadIdx.x >> 5;
    #pragma unroll
    for (int o = 16; o; o >>= 1) v += __shfl_xor_sync(0xffffffffu, v, o);
    if (lane == 0) red[w] = v;
    __syncthreads();
    float t = (threadIdx.x < (blockDim.x >> 5)) ? red[threadIdx.x] : 0.f;
    if (w == 0) {
        #pragma unroll
        for (int o = 16; o; o >>= 1) t += __shfl_xor_sync(0xffffffffu, t, o);
        if (lane == 0) red[0] = t;
    }
    __syncthreads();
    return red[0];
}
__device__ __forceinline__ float blockReduceMax(float v, float* red) {
    int lane = threadIdx.x & 31, w = threadIdx.x >> 5;
    #pragma unroll
    for (int o = 16; o; o >>= 1) v = fmaxf(v, __shfl_xor_sync(0xffffffffu, v, o));
    if (lane == 0) red[w] = v;
    __syncthreads();
    float t = (threadIdx.x < (blockDim.x >> 5)) ? red[threadIdx.x] : 0.f;
    if (w == 0) {
        #pragma unroll
        for (int o = 16; o; o >>= 1) t = fmaxf(t, __shfl_xor_sync(0xffffffffu, t, o));
        if (lane == 0) red[0] = t;
    }
    __syncthreads();
    return red[0];
}

// ---------------- weight prep: transpose fp32 --------------------------------------
__global__ void trans_all(const float* __restrict__ Wq, const float* __restrict__ Wk,
                          const float* __restrict__ Wv, const float* __restrict__ Wo,
                          const float* __restrict__ Wi, const float* __restrict__ Wf)
{
    __shared__ float tsm[32][33];
    int t = blockIdx.x;
    int l = t / 6912, r = t % 6912;
    const float* src; float* dst;
    int K, N, rowoff, nx, ky;
    if (r < 1728) {
        int w = r / 576, q2 = r % 576;
        src = (w == 0 ? Wq : w == 1 ? Wk : Wv) + (size_t)l * DD * DD;
        dst = g_WTq + (size_t)l * NQKV * DD;
        K = DD; N = DD; rowoff = w * DD; ky = q2 / 24; nx = q2 % 24;
    } else if (r < 2304) {
        int q2 = r - 1728;
        src = Wo + (size_t)l * DD * DD; dst = g_WTo + (size_t)l * DD * DD;
        K = DD; N = DD; rowoff = 0; ky = q2 / 24; nx = q2 % 24;
    } else if (r < 4608) {
        int q2 = r - 2304;
        src = Wi + (size_t)l * DD * FFD; dst = g_WTi + (size_t)l * (size_t)FFD * DD;
        K = DD; N = FFD; rowoff = 0; ky = q2 / 96; nx = q2 % 96;
    } else {
        int q2 = r - 4608;
        src = Wf + (size_t)l * FFD * DD; dst = g_WTf + (size_t)l * DD * FFD;
        K = FFD; N = DD; rowoff = 0; ky = q2 / 24; nx = q2 % 24;
    }
    int n0 = nx * 32, k0 = ky * 32;
    int tx = threadIdx.x;
    for (int i = threadIdx.y; i < 32; i += 8)
        tsm[i][tx] = src[(size_t)(k0 + i) * N + n0 + tx];
    __syncthreads();
    for (int i = threadIdx.y; i < 32; i += 8)
        dst[(size_t)(rowoff + n0 + i) * K + k0 + tx] = tsm[tx][i];
}

// ---------------- weight row quantize ------------------------------------------------
__global__ void wquant(void)
{
    __shared__ float red[32];
    int bid = blockIdx.x, tid = threadIdx.x;
    int l = bid / 6912, r = bid % 6912;
    const float* xr; int8_t *q1, *q2; float* sc; int K;
    if (r < 2304) {
        size_t o = (size_t)l * NQKV * DD + (size_t)r * DD;
        xr = g_WTq + o; q1 = g_wq1_q + o; q2 = g_wq2_q + o; sc = g_ws_q + l * NQKV + r; K = DD;
    } else if (r < 3072) {
        int rr = r - 2304;
        size_t o = (size_t)l * DD * DD + (size_t)rr * DD;
        xr = g_WTo + o; q1 = g_wq1_o + o; q2 = g_wq2_o + o; sc = g_ws_o + l * DD + rr; K = DD;
    } else if (r < 6144) {
        int rr = r - 3072;
        size_t o = (size_t)l * (size_t)FFD * DD + (size_t)rr * DD;
        xr = g_WTi + o; q1 = g_wq1_i + o; q2 = g_wq2_i + o; sc = g_ws_i + l * FFD + rr; K = DD;
    } else {
        int rr = r - 6144;
        size_t o = (size_t)l * DD * FFD + (size_t)rr * FFD;
        xr = g_WTf + o; q1 = g_wq1_f + o; q2 = g_wq2_f + o; sc = g_ws_f + l * DD + rr; K = FFD;
    }
    float mx = 0.f;
    for (int k = tid; k < K; k += 256) mx = fmaxf(mx, fabsf(xr[k]));
    mx = blockReduceMax(mx, red);
    float s = (mx > 0.f) ? mx / 127.f : 1.f;
    float inv = 1.f / s;
    for (int k = tid; k < K; k += 256) quant2(xr[k], inv, q1[k], q2[k]);
    if (tid == 0) *sc = s;
}

// ---------------- activation row quantize --------------------------------------------
__global__ void rowquant(const float* __restrict__ x, int K,
                         int8_t* __restrict__ q1, int8_t* __restrict__ q2,
                         float* __restrict__ sc)
{
    __shared__ float red[32];
    int row = blockIdx.x, tid = threadIdx.x;
    const float* xr = x + (size_t)row * K;
    float mx = 0.f;
    for (int k = tid; k < K; k += 256) mx = fmaxf(mx, fabsf(xr[k]));
    mx = blockReduceMax(mx, red);
    float s = (mx > 0.f) ? mx / 127.f : 1.f;
    float inv = 1.f / s;
    size_t o = (size_t)row * K;
    for (int k = tid; k < K; k += 256) quant2(xr[k], inv, q1[o + k], q2[o + k]);
    if (tid == 0) sc[row] = s;
}

__global__ void fuse_bias(const float* __restrict__ bq, const float* __restrict__ bk,
                          const float* __restrict__ bv)
{
    int i = blockIdx.x * 256 + threadIdx.x;
    if (i >= LL * NQKV) return;
    int l = i / NQKV, n = i % NQKV;
    g_bqkv[i] = (n < DD) ? bq[l * DD + n]
              : (n < 2 * DD) ? bk[l * DD + n - DD]
                             : bv[l * DD + n - 2 * DD];
}

// ---------------- embedding LN (+quant) ----------------------------------------------
__global__ void embed_ln_kernel(const int* __restrict__ ids, const float* __restrict__ we,
                                const float* __restrict__ pe, const float* __restrict__ te,
                                const float* __restrict__ gam, const float* __restrict__ bet,
                                float* __restrict__ out)
{
    __shared__ float xs[DD];
    __shared__ float red[32];
    int tok = blockIdx.x, s = tok & (SS - 1), id = ids[tok], tid = threadIdx.x;
    const float* wrow = we + (size_t)id * DD;
    const float* prow = pe + (size_t)s * DD;
    float sum = 0.f;
    for (int d = tid; d < DD; d += 256) {
        float v = wrow[d] + prow[d] + te[d];
        xs[d] = v; sum += v;
    }
    float mu = blockReduceSum(sum, red) * (1.0f / DD);
    float vs = 0.f;
    for (int d = tid; d < DD; d += 256) { float dl = xs[d] - mu; vs += dl * dl; }
    float var = blockReduceSum(vs, red) * (1.0f / DD);
    float r = rsqrtf(var + 1e-12f);
    size_t ro = (size_t)tok * DD;
    float mx = 0.f;
    for (int d = tid; d < DD; d += 256) {
        float o = (xs[d] - mu) * r * gam[d] + bet[d];
        out[ro + d] = o;
        mx = fmaxf(mx, fabsf(o));
    }
    mx = blockReduceMax(mx, red);
    float sc = (mx > 0.f) ? mx / 127.f : 1.f;
    float inv = 1.f / sc;
    for (int d = tid; d < DD; d += 256)
        quant2(out[ro + d], inv, g_hq1[ro + d], g_hq2[ro + d]);
    if (tid == 0) g_hs[tok] = sc;
}

// ---------------- LN over (p0+p1+p2+bias+res) (+quant) -------------------------------
__global__ void ln_sum3_kernel(const float* __restrict__ p0, const float* __restrict__ p1,
                               const float* __restrict__ p2,
                               const float* __restrict__ bias, const float* __restrict__ res,
                               const float* __restrict__ gam, const float* __restrict__ bet,
                               float* __restrict__ out)
{
    __shared__ float xs[DD];
    __shared__ float red[32];
    int row = blockIdx.x, tid = threadIdx.x;
    size_t ro = (size_t)row * DD;
    float sum = 0.f;
    for (int d = tid; d < DD; d += 256) {
        float v = p0[ro + d] + p1[ro + d] + p2[ro + d] + bias[d] + res[ro + d];
        xs[d] = v; sum += v;
    }
    float mu = blockReduceSum(sum, red) * (1.0f / DD);
    float vs = 0.f;
    for (int d = tid; d < DD; d += 256) { float dl = xs[d] - mu; vs += dl * dl; }
    float var = blockReduceSum(vs, red) * (1.0f / DD);
    float r = rsqrtf(var + 1e-12f);
    float mx = 0.f;
    for (int d = tid; d < DD; d += 256) {
        float o = (xs[d] - mu) * r * gam[d] + bet[d];
        out[ro + d] = o; xs[d] = o;
        mx = fmaxf(mx, fabsf(o));
    }
    mx = blockReduceMax(mx, red);
    float sc = (mx > 0.f) ? mx / 127.f : 1.f;
    float inv = 1.f / sc;
    for (int d = tid; d < DD; d += 256)
        quant2(xs[d], inv, g_hq1[ro + d], g_hq2[ro + d]);
    if (tid == 0) g_hs[row] = sc;
}

// ---------------- int8 2-level GEMM ---------------------------------------------------
// CTA 128x64, warp tile 32x32 (wm = wid&3, wn = wid>>2). Stage = 64-K, 24KB, 3 stages.
// mode 0: fp32 partial -> Cz ; mode 1: +bias,GELU -> C fp32 ; mode 3: QKV -> Ch/Cl bf16
#define I8STG 3
#define I8_SMEM (I8STG*24576 + 1024)

__global__ __launch_bounds__(256, 2)
void gemm_i8(const int8_t* __restrict__ A1, const int8_t* __restrict__ A2,
             const float* __restrict__ As,
             const int8_t* __restrict__ B1, const int8_t* __restrict__ B2,
             const float* __restrict__ Bs,
             const float* __restrict__ bias,
             float* __restrict__ C, float* __restrict__ C2f, float* __restrict__ C3f,
             __nv_bfloat16* __restrict__ Ch, __nv_bfloat16* __restrict__ Cl,
             int N, int K, int lda, int mode)
{
    extern __shared__ char dsm[];
    uint32_t raw = smem_u32(dsm);
    uint32_t s0 = (raw + 1023) & ~1023u;

    int tid = threadIdx.x, wid = tid >> 5, lane = tid & 31;
    int wm = wid & 3, wn = wid >> 2;
    long mBase = (long)blockIdx.y * 128;
    long nBase = (long)blockIdx.x * 64;
    int kOff = blockIdx.z * K;

    int acc1[2][4][4], acc2[2][4][4];
    #pragma unroll
    for (int i = 0; i < 2; i++)
        #pragma unroll
        for (int j = 0; j < 4; j++)
            #pragma unroll
            for (int q = 0; q < 4; q++) { acc1[i][j][q] = 0; acc2[i][j][q] = 0; }

    // loaders: A 128x64B (512 x16B -> 2/thread), B 64x64B (256 -> 1/thread)
    int arow_l = tid >> 2, ac_l = (tid & 3) * 16;
    int arow_l2 = (tid + 256) >> 2, ac_l2 = ((tid + 256) & 3) * 16;  // wait: same pattern shifted
    const int8_t* A1p = A1 + (size_t)(mBase + 0) * lda + kOff;
    const int8_t* A2p = A2 + (size_t)(mBase + 0) * lda + kOff;
    const int8_t* B1p = B1 + (size_t)(nBase + 0) * lda + kOff;
    const int8_t* B2p = B2 + (size_t)(nBase + 0) * lda + kOff;
    const int nIt = K / 64;

    auto ld_stage = [&](int it) {
        uint32_t sb = s0 + (it % I8STG) * 24576;
        int k0 = it * 64;
        #pragma unroll
        for (int r2 = 0; r2 < 2; r2++) {
            int idx = tid + r2 * 256;
            int row = idx >> 2, c = (idx & 3) * 16;
            uint32_t sw = swz(row * 64 + c);
            cpa16(sb + sw,        A1p + (size_t)row * lda + k0 + c);
            cpa16(sb + 8192 + sw, A2p + (size_t)row * lda + k0 + c);
        }
        {
            int row = tid >> 2, c = (tid & 3) * 16;
            uint32_t sw = swz(row * 64 + c);
            cpa16(sb + 16384 + sw, B1p + (size_t)row * lda + k0 + c);
            cpa16(sb + 20480 + sw, B2p + (size_t)row * lda + k0 + c);
        }
        cp_commit();
    };

    ld_stage(0); ld_stage(1);

    #pragma unroll 1
    for (int it = 0; it < nIt; ++it) {
        if (it < nIt - 1) cp_wait<1>(); else cp_wait<0>();
        __syncthreads();
        if (it + 2 < nIt) ld_stage(it + 2);

        uint32_t base = s0 + (it % I8STG) * 24576;
        #pragma unroll
        for (int kc = 0; kc < 2; kc++) {
            uint32_t kcol = kc * 32 + (lane >> 4) * 16;
            int brow = wn * 32 + (lane & 15);
            uint32_t b1[4][2], b2[4][2];
            #pragma unroll
            for (int n2 = 0; n2 < 2; n2++) {
                uint32_t r0, r1, r2, r3;
                ldsm4(r0, r1, r2, r3, base + 16384 + swz((brow + n2 * 16) * 64 + kcol));
                b1[n2*2][0] = r0; b1[n2*2][1] = r2; b1[n2*2+1][0] = r1; b1[n2*2+1][1] = r3;
                ldsm4(r0, r1, r2, r3, base + 20480 + swz((brow + n2 * 16) * 64 + kcol));
                b2[n2*2][0] = r0; b2[n2*2][1] = r2; b2[n2*2+1][0] = r1; b2[n2*2+1][1] = r3;
            }
            int arow = wm * 32 + (lane & 15);
            #pragma unroll
            for (int mt = 0; mt < 2; mt++) {
                uint32_t a1[4], a2[4];
                ldsm4(a1[0], a1[1], a1[2], a1[3], base + swz((arow + mt * 16) * 64 + kcol));
                ldsm4(a2[0], a2[1], a2[2], a2[3], base + 8192 + swz((arow + mt * 16) * 64 + kcol));
                #pragma unroll
                for (int nt = 0; nt < 4; nt++) mma_s8(acc1[mt][nt], a1, b1[nt]);
                #pragma unroll
                for (int nt = 0; nt < 4; nt++) mma_s8(acc2[mt][nt], a1, b2[nt]);
                #pragma unroll
                for (int nt = 0; nt < 4; nt++) mma_s8(acc2[mt][nt], a2, b1[nt]);
            }
        }
    }

    float* dst = (blockIdx.z == 0) ? C : (blockIdx.z == 1 ? C2f : C3f);
    #pragma unroll
    for (int mt = 0; mt < 2; mt++) {
        #pragma unroll
        for (int half = 0; half < 2; half++) {
            long m = mBase + wm * 32 + mt * 16 + (lane >> 2) + half * 8;
            float sa = __ldg(As + m);
            #pragma unroll
            for (int nt = 0; nt < 4; nt++) {
                long n0 = nBase + wn * 32 + nt * 8 + (lane & 3) * 2;
                float f0 = (float)acc1[mt][nt][half*2]   + (float)acc2[mt][nt][half*2]   * (1.f/256.f);
                float f1 = (float)acc1[mt][nt][half*2+1] + (float)acc2[mt][nt][half*2+1] * (1.f/256.f);
                float v0 = sa * __ldg(Bs + n0)     * f0;
                float v1 = sa * __ldg(Bs + n0 + 1) * f1;
                if (mode == 0) {
                    *(float2*)(dst + m * N + n0) = make_float2(v0, v1);
                } else if (mode == 1) {
                    v0 += __ldg(bias + n0); v1 += __ldg(bias + n0 + 1);
                    v0 = 0.5f * v0 * (1.0f + erff(v0 * 0.70710678118654752f));
                    v1 = 0.5f * v1 * (1.0f + erff(v1 * 0.70710678118654752f));
                    *(float2*)(C + m * N + n0) = make_float2(v0, v1);
                } else {
                    v0 += __ldg(bias + n0); v1 += __ldg(bias + n0 + 1);
                    float sc2 = (n0 < DD) ? 0.125f : 1.0f;
                    uint32_t ph, pl; pack2(v0 * sc2, v1 * sc2, ph, pl);
                    *(uint32_t*)(Ch + m * N + n0) = ph;
                    *(uint32_t*)(Cl + m * N + n0) = pl;
                }
            }
        }
    }
}

// ---------------- flash attention (R10 version; fp32 ctx out) -------------------------
#define A_QH 0
#define A_QL 16384
#define A_KV 32768
#define A_MK (32768 + 98304)
#define ATTN_SMEM (131072 + 2048 + 1024)

__global__ __launch_bounds__(256, 1)
void attn_flash(const __nv_bfloat16* __restrict__ qkv_h,
                const __nv_bfloat16* __restrict__ qkv_l,
                const int* __restrict__ mask, float* __restrict__ ctx)
{
    extern __shared__ char dsm[];
    uint32_t raw = smem_u32(dsm);
    uint32_t s0 = (raw + 1023) & ~1023u;
    char* sm = dsm + (s0 - raw);

    int b = blockIdx.z, h = blockIdx.y, qt = blockIdx.x;
    int tid = threadIdx.x, wid = tid >> 5, lane = tid & 31;
    int q0 = b * SS + qt * 128;
    int k0g = b * SS;

    float* maskf = (float*)(sm + A_MK);
    for (int i = tid; i < SS; i += 256) maskf[i] = (float)mask[b * SS + i];

    #pragma unroll
    for (int r2 = 0; r2 < 4; r2++) {
        int i = tid + r2 * 256;
        int row = i >> 3, c = i & 7;
        uint32_t sw = swz(row * 128 + c * 16);
        size_t gq = (size_t)(q0 + row) * NQKV + h * DH + c * 8;
        cpa16(s0 + A_QH + sw, qkv_h + gq);
        cpa16(s0 + A_QL + sw, qkv_l + gq);
    }
    cp_commit();

    auto ldKV = [&](int ch, int stg) {
        uint32_t kb = s0 + A_KV + stg * 32768;
        #pragma unroll
        for (int r2 = 0; r2 < 2; r2++) {
            int i = tid + r2 * 256;
            int row = i >> 3, c = i & 7;
            uint32_t sw = swz(row * 128 + c * 16);
            size_t gk = (size_t)(k0g + ch * 64 + row) * NQKV + DD + h * DH + c * 8;
            cpa16(kb + sw,         qkv_h + gk);
            cpa16(kb + 8192 + sw,  qkv_l + gk);
            cpa16(kb + 16384 + sw, qkv_h + gk + DD);
            cpa16(kb + 24576 + sw, qkv_l + gk + DD);
        }
        cp_commit();
    };
    ldKV(0, 0);
    ldKV(1, 1);
    cp_wait<2>(); __syncthreads();

    uint32_t qh[4][4], ql[4][4];
    {
        int qr = wid * 16 + (lane & 15);
        #pragma unroll
        for (int ks = 0; ks < 4; ks++) {
            uint32_t o2 = swz(qr * 128 + (ks * 2 + (lane >> 4)) * 16);
            ldsm4(qh[ks][0], qh[ks][1], qh[ks][2], qh[ks][3], s0 + A_QH + o2);
            ldsm4(ql[ks][0], ql[ks][1], ql[ks][2], ql[ks][3], s0 + A_QL + o2);
        }
    }

    float M[2] = {-1e30f, -1e30f}, Zs[2] = {0.f, 0.f}, Zm[2] = {0.f, 0.f};
    float o[8][4];
    #pragma unroll
    for (int i = 0; i < 8; i++)
        #pragma unroll
        for (int j = 0; j < 4; j++) o[i][j] = 0.f;

    #pragma unroll 1
    for (int ch = 0; ch < 8; ch++) {
        if (ch < 7) cp_wait<1>(); else cp_wait<0>();
        __syncthreads();
        if (ch + 2 < 8) ldKV(ch + 2, (ch + 2) % 3);

        uint32_t kb = s0 + A_KV + (ch % 3) * 32768;
        float s[8][4];
        #pragma unroll
        for (int i = 0; i < 8; i++)
            #pragma unroll
            for (int j = 0; j < 4; j++) s[i][j] = 0.f;

        #pragma unroll
        for (int n4 = 0; n4 < 4; n4++) {
            int br = n4 * 16 + (lane & 15);
            #pragma unroll
            for (int ks = 0; ks < 4; ks++) {
                uint32_t kcol = (ks * 2 + (lane >> 4)) * 16;
                uint32_t r0, r1, r2, r3;
                uint32_t bh0[2], bh1[2], bl0[2], bl1[2];
                ldsm4(r0, r1, r2, r3, kb + swz(br * 128 + kcol));
                bh0[0] = r0; bh0[1] = r2; bh1[0] = r1; bh1[1] = r3;
                ldsm4(r0, r1, r2, r3, kb + 8192 + swz(br * 128 + kcol));
                bl0[0] = r0; bl0[1] = r2; bl1[0] = r1; bl1[1] = r3;
                mma_bf16(s[n4*2], qh[ks], bh0);  mma_bf16(s[n4*2+1], qh[ks], bh1);
                mma_bf16(s[n4*2], qh[ks], bl0);  mma_bf16(s[n4*2+1], qh[ks], bl1);
                mma_bf16(s[n4*2], ql[ks], bh0);  mma_bf16(s[n4*2+1], ql[ks], bh1);
            }
        }

        #pragma unroll
        for (int g = 0; g < 2; g++) {
            float mx = -1e30f;
            #pragma unroll
            for (int nt = 0; nt < 8; nt++)
                mx = fmaxf(mx, fmaxf(s[nt][2*g], s[nt][2*g+1]));
            mx = fmaxf(mx, __shfl_xor_sync(0xffffffffu, mx, 1));
            mx = fmaxf(mx, __shfl_xor_sync(0xffffffffu, mx, 2));
            float Mn = fmaxf(M[g], mx);
            float fac = __expf(M[g] - Mn);
            float zc = 0.f, zmc = 0.f;
            #pragma unroll
            for (int nt = 0; nt < 8; nt++) {
                #pragma unroll
                for (int e = 0; e < 2; e++) {
                    int col = ch * 64 + nt * 8 + (lane & 3) * 2 + e;
                    float ex = __expf(s[nt][2*g+e] - Mn);
                    float mm = maskf[col];
                    zc += ex; zmc += ex * mm;
                    s[nt][2*g+e] = ex * mm;
                }
            }
            zc += __shfl_xor_sync(0xffffffffu, zc, 1);
            zc += __shfl_xor_sync(0xffffffffu, zc, 2);
            zmc += __shfl_xor_sync(0xffffffffu, zmc, 1);
            zmc += __shfl_xor_sync(0xffffffffu, zmc, 2);
            Zs[g] = Zs[g] * fac + zc;
            Zm[g] = Zm[g] * fac + zmc;
            M[g] = Mn;
            #pragma unroll
            for (int nt = 0; nt < 8; nt++) { o[nt][2*g] *= fac; o[nt][2*g+1] *= fac; }
        }

        uint32_t ah[4][4], al[4][4];
        #pragma unroll
        for (int kt = 0; kt < 4; kt++) {
            pack2(s[2*kt][0],   s[2*kt][1],   ah[kt][0], al[kt][0]);
            pack2(s[2*kt][2],   s[2*kt][3],   ah[kt][1], al[kt][1]);
            pack2(s[2*kt+1][0], s[2*kt+1][1], ah[kt][2], al[kt][2]);
            pack2(s[2*kt+1][2], s[2*kt+1][3], ah[kt][3], al[kt][3]);
        }

        uint32_t vb = kb + 16384;
        #pragma unroll
        for (int n4 = 0; n4 < 4; n4++) {
            #pragma unroll
            for (int kt = 0; kt < 4; kt++) {
                uint32_t addr = swz((kt * 16 + (lane & 15)) * 128 + n4 * 32 + (lane >> 4) * 16);
                uint32_t r0, r1, r2, r3;
                uint32_t bh0[2], bh1[2], bl0[2], bl1[2];
                ldsm4t(r0, r1, r2, r3, vb + addr);
                bh0[0] = r0; bh0[1] = r1; bh1[0] = r2; bh1[1] = r3;
                ldsm4t(r0, r1, r2, r3, vb + 8192 + addr);
                bl0[0] = r0; bl0[1] = r1; bl1[0] = r2; bl1[1] = r3;
                mma_bf16(o[n4*2], ah[kt], bh0);  mma_bf16(o[n4*2+1], ah[kt], bh1);
                mma_bf16(o[n4*2], ah[kt], bl0);  mma_bf16(o[n4*2+1], ah[kt], bl1);
                mma_bf16(o[n4*2], al[kt], bh0);  mma_bf16(o[n4*2+1], al[kt], bh1);
            }
        }
    }

    #pragma unroll
    for (int g = 0; g < 2; g++) {
        float den = fmaxf(Zm[g], 1e-9f * Zs[g]);
        float rcp = 1.0f / den;
        size_t row = q0 + wid * 16 + (lane >> 2) + g * 8;
        #pragma unroll
        for (int nt = 0; nt < 8; nt++) {
            int col = h * DH + nt * 8 + (lane & 3) * 2;
            *(float2*)(ctx + row * DD + col) =
                make_float2(o[nt][2*g] * rcp, o[nt][2*g+1] * rcp);
        }
    }
}

// ---------------- pool + normalize ----------------------------------------------------
__global__ void pool_kernel(const float* __restrict__ h, const int* __restrict__ mask,
                            float* __restrict__ out)
{
    __shared__ float sent[DD];
    __shared__ float red[32];
    int b = blockIdx.x, tid = threadIdx.x;
    float ms = 0.f;
    for (int s = tid; s < SS; s += 256) ms += (float)mask[b * SS + s];
    ms = blockReduceSum(ms, red);
    float inv = 1.0f / fmaxf(ms, 1e-6f);
    for (int d = tid; d < DD; d += 256) {
        float a = 0.f;
        const float* hp = h + ((size_t)b * SS) * DD + d;
        const int* mp = mask + b * SS;
        for (int s = 0; s < SS; s++) a += hp[(size_t)s * DD] * (float)mp[s];
        sent[d] = a * inv;
    }
    __syncthreads();
    float sq = 0.f;
    for (int d = tid; d < DD; d += 256) sq += sent[d] * sent[d];
    sq = blockReduceSum(sq, red);
    float rn = 1.0f / fmaxf(sqrtf(sq), 1e-12f);
    for (int d = tid; d < DD; d += 256) out[b * DD + d] = sent[d] * rn;
}

// ---------------- launch ---------------------------------------------------------------
extern "C" void kernel_launch(void* const* d_in, const int* in_sizes, int n_in,
                              void* d_out, int out_size)
{
    const int*   input_ids = (const int*)  d_in[0];
    const int*   amask     = (const int*)  d_in[1];
    const float* word_emb  = (const float*)d_in[2];
    const float* pos_emb   = (const float*)d_in[3];
    const float* type_emb  = (const float*)d_in[4];
    const float* emb_g     = (const float*)d_in[5];
    const float* emb_b     = (const float*)d_in[6];
    const float* Wq = (const float*)d_in[7];  const float* bq = (const float*)d_in[8];
    const float* Wk = (const float*)d_in[9];  const float* bk = (const float*)d_in[10];
    const float* Wv = (const float*)d_in[11]; const float* bv = (const float*)d_in[12];
    const float* Wo = (const float*)d_in[13]; const float* bo = (const float*)d_in[14];
    const float* ln1g = (const float*)d_in[15]; const float* ln1b = (const float*)d_in[16];
    const float* Wi = (const float*)d_in[17]; const float* bi = (const float*)d_in[18];
    const float* Wf = (const float*)d_in[19]; const float* bf = (const float*)d_in[20];
    const float* ln2g = (const float*)d_in[21]; const float* ln2b = (const float*)d_in[22];
    float* out = (float*)d_out;

    float *p_h, *p_t1, *p_t2, *p_t3, *p_ctx, *p_ff, *p_bqkv;
    float *p_hs, *p_cs, *p_fs, *ws_q, *ws_o, *ws_i, *ws_f;
    int8_t *hq1, *hq2, *cq1, *cq2, *fq1, *fq2;
    int8_t *wq1q, *wq2q, *wq1o, *wq2o, *wq1i, *wq2i, *wq1f, *wq2f;
    __nv_bfloat16 *p_qh, *p_ql;
    cudaGetSymbolAddress((void**)&p_h,  g_h);
    cudaGetSymbolAddress((void**)&p_t1, g_t1);
    cudaGetSymbolAddress((void**)&p_t2, g_t2);
    cudaGetSymbolAddress((void**)&p_t3, g_t3);
    cudaGetSymbolAddress((void**)&p_ctx, g_ctx);
    cudaGetSymbolAddress((void**)&p_ff, g_ff);
    cudaGetSymbolAddress((void**)&p_bqkv, g_bqkv);
    cudaGetSymbolAddress((void**)&p_hs, g_hs);
    cudaGetSymbolAddress((void**)&p_cs, g_cs);
    cudaGetSymbolAddress((void**)&p_fs, g_fs);
    cudaGetSymbolAddress((void**)&hq1, g_hq1); cudaGetSymbolAddress((void**)&hq2, g_hq2);
    cudaGetSymbolAddress((void**)&cq1, g_cq1); cudaGetSymbolAddress((void**)&cq2, g_cq2);
    cudaGetSymbolAddress((void**)&fq1, g_fq1); cudaGetSymbolAddress((void**)&fq2, g_fq2);
    cudaGetSymbolAddress((void**)&wq1q, g_wq1_q); cudaGetSymbolAddress((void**)&wq2q, g_wq2_q);
    cudaGetSymbolAddress((void**)&wq1o, g_wq1_o); cudaGetSymbolAddress((void**)&wq2o, g_wq2_o);
    cudaGetSymbolAddress((void**)&wq1i, g_wq1_i); cudaGetSymbolAddress((void**)&wq2i, g_wq2_i);
    cudaGetSymbolAddress((void**)&wq1f, g_wq1_f); cudaGetSymbolAddress((void**)&wq2f, g_wq2_f);
    cudaGetSymbolAddress((void**)&ws_q, g_ws_q); cudaGetSymbolAddress((void**)&ws_o, g_ws_o);
    cudaGetSymbolAddress((void**)&ws_i, g_ws_i); cudaGetSymbolAddress((void**)&ws_f, g_ws_f);
    cudaGetSymbolAddress((void**)&p_qh, g_qkv_h); cudaGetSymbolAddress((void**)&p_ql, g_qkv_l);

    cudaFuncSetAttribute(gemm_i8, cudaFuncAttributeMaxDynamicSharedMemorySize, I8_SMEM);
    cudaFuncSetAttribute(attn_flash, cudaFuncAttributeMaxDynamicSharedMemorySize, ATTN_SMEM);

    trans_all<<<LL * 6912, dim3(32, 8)>>>(Wq, Wk, Wv, Wo, Wi, Wf);
    wquant<<<LL * 6912, 256>>>();
    fuse_bias<<<(LL * NQKV + 255) / 256, 256>>>(bq, bk, bv);
    embed_ln_kernel<<<MTOK, 256>>>(input_ids, word_emb, pos_emb, type_emb,
                                   emb_g, emb_b, p_h);

    dim3 gQKV(NQKV / 64, MTOK / 128, 1);
    dim3 gSK3(DD   / 64, MTOK / 128, 3);
    dim3 gFF (FFD  / 64, MTOK / 128, 1);

    for (int l = 0; l < LL; l++) {
        size_t wdd = (size_t)l * DD * DD;
        size_t wdf = (size_t)l * (size_t)DD * FFD;
        size_t wqk = (size_t)l * NQKV * DD;

        gemm_i8<<<gQKV, 256, I8_SMEM>>>(hq1, hq2, p_hs,
                                        wq1q + wqk, wq2q + wqk, ws_q + l * NQKV,
                                        p_bqkv + l * NQKV, nullptr, nullptr, nullptr,
                                        p_qh, p_ql, NQKV, DD, DD, 3);

        attn_flash<<<dim3(4, HH, BB), 256, ATTN_SMEM>>>(p_qh, p_ql, amask, p_ctx);
        rowquant<<<MTOK, 256>>>(p_ctx, DD, cq1, cq2, p_cs);

        gemm_i8<<<gSK3, 256, I8_SMEM>>>(cq1, cq2, p_cs,
                                        wq1o + wdd, wq2o + wdd, ws_o + l * DD,
                                        nullptr, p_t1, p_t2, p_t3, nullptr, nullptr,
                                        DD, DD / 3, DD, 0);
        ln_sum3_kernel<<<MTOK, 256>>>(p_t1, p_t2, p_t3, bo + l * DD, p_h,
                                      ln1g + l * DD, ln1b + l * DD, p_h);

        gemm_i8<<<gFF, 256, I8_SMEM>>>(hq1, hq2, p_hs,
                                       wq1i + wdf, wq2i + wdf, ws_i + l * FFD,
                                       bi + l * FFD, p_ff, nullptr, nullptr, nullptr, nullptr,
                                       FFD, DD, DD, 1);
        rowquant<<<MTOK, 256>>>(p_ff, FFD, fq1, fq2, p_fs);

        gemm_i8<<<gSK3, 256, I8_SMEM>>>(fq1, fq2, p_fs,
                                        wq1f + wdf, wq2f + wdf, ws_f + l * DD,
                                        nullptr, p_t1, p_t2, p_t3, nullptr, nullptr,
                                        DD, FFD / 3, FFD, 0);
        ln_sum3_kernel<<<MTOK, 256>>>(p_t1, p_t2, p_t3, bf + l * DD, p_h,
                                      ln2g + l * DD, ln2b + l * DD, p_h);
    }

    pool_kernel<<<BB, 256>>>(p_h, amask, out);
}

// round 13
// speedup vs baseline: 1.7592x; 1.7592x over previous
#include <cuda_runtime.h>
#include <cuda_bf16.h>
#include <math.h>
#include <stdint.h>

#define BB 8
#define SS 512
#define DD 768
#define HH 12
#define DH 64
#define LL 12
#define FFD 3072
#define MTOK (BB*SS)
#define NQKV 2304

__device__ __align__(256) float g_h  [MTOK*DD];
__device__ __align__(256) float g_t1 [MTOK*DD];
__device__ __align__(256) float g_t2 [MTOK*DD];
__device__ __align__(256) float g_t3 [MTOK*DD];

__device__ __align__(256) __nv_bfloat16 g_h_hi [MTOK*DD];
__device__ __align__(256) __nv_bfloat16 g_h_lo [MTOK*DD];
__device__ __align__(256) __nv_bfloat16 g_qkv_h[MTOK*NQKV];
__device__ __align__(256) __nv_bfloat16 g_qkv_l[MTOK*NQKV];
__device__ __align__(256) __nv_bfloat16 g_ctx_hi[MTOK*DD];
__device__ __align__(256) __nv_bfloat16 g_ctx_lo[MTOK*DD];
__device__ __align__(256) __nv_bfloat16 g_ff_hi[MTOK*FFD];
__device__ __align__(256) __nv_bfloat16 g_ff_lo[MTOK*FFD];

__device__ __align__(256) __nv_bfloat16 g_Wqkv_h[LL*NQKV*DD];
__device__ __align__(256) __nv_bfloat16 g_Wqkv_l[LL*NQKV*DD];
__device__ __align__(256) __nv_bfloat16 g_WoT_h[LL*DD*DD];
__device__ __align__(256) __nv_bfloat16 g_WoT_l[LL*DD*DD];
__device__ __align__(256) __nv_bfloat16 g_WiT_h[LL*DD*FFD];
__device__ __align__(256) __nv_bfloat16 g_WiT_l[LL*DD*FFD];
__device__ __align__(256) __nv_bfloat16 g_WfT_h[LL*DD*FFD];
__device__ __align__(256) __nv_bfloat16 g_WfT_l[LL*DD*FFD];
__device__ __align__(256) float g_bqkv[LL*NQKV];

// ---------------- helpers ------------------------------------------------------
__device__ __forceinline__ uint32_t smem_u32(const void* p) {
    uint32_t a;
    asm("{ .reg .u64 t; cvta.to.shared.u64 t, %1; cvt.u32.u64 %0, t; }" : "=r"(a) : "l"(p));
    return a;
}
__device__ __forceinline__ uint32_t swz(uint32_t o) { return o ^ ((o >> 3) & 0x70); }
__device__ __forceinline__ void cpa16(uint32_t saddr, const void* g) {
    asm volatile("cp.async.cg.shared.global [%0], [%1], 16;" :: "r"(saddr), "l"(g));
}
__device__ __forceinline__ void cp_commit() {
    asm volatile("cp.async.commit_group;" ::: "memory");
}
template <int N>
__device__ __forceinline__ void cp_wait() {
    asm volatile("cp.async.wait_group %0;" :: "n"(N) : "memory");
}
__device__ __forceinline__ void ldsm4(uint32_t& r0, uint32_t& r1, uint32_t& r2, uint32_t& r3,
                                      uint32_t addr) {
    asm volatile("ldmatrix.sync.aligned.m8n8.x4.shared.b16 {%0,%1,%2,%3}, [%4];"
                 : "=r"(r0), "=r"(r1), "=r"(r2), "=r"(r3) : "r"(addr));
}
__device__ __forceinline__ void ldsm4t(uint32_t& r0, uint32_t& r1, uint32_t& r2, uint32_t& r3,
                                       uint32_t addr) {
    asm volatile("ldmatrix.sync.aligned.m8n8.x4.trans.shared.b16 {%0,%1,%2,%3}, [%4];"
                 : "=r"(r0), "=r"(r1), "=r"(r2), "=r"(r3) : "r"(addr));
}
__device__ __forceinline__ void mma_bf16(float* d, const uint32_t* a, const uint32_t* b) {
    asm volatile("mma.sync.aligned.m16n8k16.row.col.f32.bf16.bf16.f32 "
                 "{%0,%1,%2,%3}, {%4,%5,%6,%7}, {%8,%9}, {%0,%1,%2,%3};"
                 : "+f"(d[0]), "+f"(d[1]), "+f"(d[2]), "+f"(d[3])
                 : "r"(a[0]), "r"(a[1]), "r"(a[2]), "r"(a[3]), "r"(b[0]), "r"(b[1]));
}
__device__ __forceinline__ void split_bf16(float x, __nv_bfloat16& hi, __nv_bfloat16& lo) {
    hi = __float2bfloat16(x);
    lo = __float2bfloat16(x - __bfloat162float(hi));
}
__device__ __forceinline__ void pack2(float a, float b, uint32_t& ph, uint32_t& pl) {
    __nv_bfloat16 ha, la, hb, lb;
    split_bf16(a, ha, la); split_bf16(b, hb, lb);
    __nv_bfloat162 th(ha, hb), tl(la, lb);
    ph = *(uint32_t*)&th; pl = *(uint32_t*)&tl;
}
__device__ __forceinline__ float blockReduceSum(float v, float* red) {
    int lane = threadIdx.x & 31, w = threadIdx.x >> 5;
    #pragma unroll
    for (int o = 16; o; o >>= 1) v += __shfl_xor_sync(0xffffffffu, v, o);
    if (lane == 0) red[w] = v;
    __syncthreads();
    float t = (threadIdx.x < (blockDim.x >> 5)) ? red[threadIdx.x] : 0.f;
    if (w == 0) {
        #pragma unroll
        for (int o = 16; o; o >>= 1) t += __shfl_xor_sync(0xffffffffu, t, o);
        if (lane == 0) red[0] = t;
    }
    __syncthreads();
    return red[0];
}

// ---------------- weight prep ------------------------------------------------------
__global__ void trans_all(const float* __restrict__ Wq, const float* __restrict__ Wk,
                          const float* __restrict__ Wv, const float* __restrict__ Wo,
                          const float* __restrict__ Wi, const float* __restrict__ Wf)
{
    __shared__ float tsm[32][33];
    int t = blockIdx.x;
    int l = t / 6912, r = t % 6912;
    const float* src; __nv_bfloat16 *dh, *dl;
    int K, N, rowoff, nx, ky;
    if (r < 1728) {
        int w = r / 576, q2 = r % 576;
        src = (w == 0 ? Wq : w == 1 ? Wk : Wv) + (size_t)l * DD * DD;
        dh = g_Wqkv_h + (size_t)l * NQKV * DD; dl = g_Wqkv_l + (size_t)l * NQKV * DD;
        K = DD; N = DD; rowoff = w * DD; ky = q2 / 24; nx = q2 % 24;
    } else if (r < 2304) {
        int q2 = r - 1728;
        src = Wo + (size_t)l * DD * DD;
        dh = g_WoT_h + (size_t)l * DD * DD; dl = g_WoT_l + (size_t)l * DD * DD;
        K = DD; N = DD; rowoff = 0; ky = q2 / 24; nx = q2 % 24;
    } else if (r < 4608) {
        int q2 = r - 2304;
        src = Wi + (size_t)l * DD * FFD;
        dh = g_WiT_h + (size_t)l * DD * FFD; dl = g_WiT_l + (size_t)l * DD * FFD;
        K = DD; N = FFD; rowoff = 0; ky = q2 / 96; nx = q2 % 96;
    } else {
        int q2 = r - 4608;
        src = Wf + (size_t)l * FFD * DD;
        dh = g_WfT_h + (size_t)l * DD * FFD; dl = g_WfT_l + (size_t)l * DD * FFD;
        K = FFD; N = DD; rowoff = 0; ky = q2 / 24; nx = q2 % 24;
    }
    int n0 = nx * 32, k0 = ky * 32;
    int tx = threadIdx.x;
    for (int i = threadIdx.y; i < 32; i += 8)
        tsm[i][tx] = src[(size_t)(k0 + i) * N + n0 + tx];
    __syncthreads();
    for (int i = threadIdx.y; i < 32; i += 8) {
        float v = tsm[tx][i];
        __nv_bfloat16 hi, lo; split_bf16(v, hi, lo);
        size_t o = (size_t)(rowoff + n0 + i) * K + k0 + tx;
        dh[o] = hi; dl[o] = lo;
    }
}

__global__ void fuse_bias(const float* __restrict__ bq, const float* __restrict__ bk,
                          const float* __restrict__ bv)
{
    int i = blockIdx.x * 256 + threadIdx.x;
    if (i >= LL * NQKV) return;
    int l = i / NQKV, n = i % NQKV;
    g_bqkv[i] = (n < DD) ? bq[l * DD + n]
              : (n < 2 * DD) ? bk[l * DD + n - DD]
                             : bv[l * DD + n - 2 * DD];
}

// ---------------- embedding LN -------------------------------------------------
__global__ void embed_ln_kernel(const int* __restrict__ ids, const float* __restrict__ we,
                                const float* __restrict__ pe, const float* __restrict__ te,
                                const float* __restrict__ gam, const float* __restrict__ bet,
                                float* __restrict__ out,
                                __nv_bfloat16* __restrict__ oh, __nv_bfloat16* __restrict__ ol)
{
    __shared__ float xs[DD];
    __shared__ float red[32];
    int tok = blockIdx.x, s = tok & (SS - 1), id = ids[tok], tid = threadIdx.x;
    const float* wrow = we + (size_t)id * DD;
    const float* prow = pe + (size_t)s * DD;
    float sum = 0.f;
    for (int d = tid; d < DD; d += 256) {
        float v = wrow[d] + prow[d] + te[d];
        xs[d] = v; sum += v;
    }
    float mu = blockReduceSum(sum, red) * (1.0f / DD);
    float vs = 0.f;
    for (int d = tid; d < DD; d += 256) { float dl = xs[d] - mu; vs += dl * dl; }
    float var = blockReduceSum(vs, red) * (1.0f / DD);
    float r = rsqrtf(var + 1e-12f);
    size_t ro = (size_t)tok * DD;
    for (int d = tid; d < DD; d += 256) {
        float o = (xs[d] - mu) * r * gam[d] + bet[d];
        out[ro + d] = o;
        __nv_bfloat16 hi, lo; split_bf16(o, hi, lo);
        oh[ro + d] = hi; ol[ro + d] = lo;
    }
}

// LN over (p0 [+ p1 [+ p2]] + bias + res); nparts selects
__global__ void ln_sum_kernel(const float* __restrict__ p0, const float* __restrict__ p1,
                              const float* __restrict__ p2, int nparts,
                              const float* __restrict__ bias, const float* __restrict__ res,
                              const float* __restrict__ gam, const float* __restrict__ bet,
                              float* __restrict__ out,
                              __nv_bfloat16* __restrict__ oh, __nv_bfloat16* __restrict__ ol)
{
    __shared__ float xs[DD];
    __shared__ float red[32];
    int row = blockIdx.x, tid = threadIdx.x;
    size_t ro = (size_t)row * DD;
    float sum = 0.f;
    for (int d = tid; d < DD; d += 256) {
        float v = p0[ro + d] + p1[ro + d] + bias[d] + res[ro + d];
        if (nparts == 3) v += p2[ro + d];
        xs[d] = v; sum += v;
    }
    float mu = blockReduceSum(sum, red) * (1.0f / DD);
    float vs = 0.f;
    for (int d = tid; d < DD; d += 256) { float dl = xs[d] - mu; vs += dl * dl; }
    float var = blockReduceSum(vs, red) * (1.0f / DD);
    float r = rsqrtf(var + 1e-12f);
    for (int d = tid; d < DD; d += 256) {
        float o = (xs[d] - mu) * r * gam[d] + bet[d];
        out[ro + d] = o;
        __nv_bfloat16 hi, lo; split_bf16(o, hi, lo);
        oh[ro + d] = hi; ol[ro + d] = lo;
    }
}

// ---------------- GEMM ----------------------------------------------------------
#define GSTG 3
#define GEMM_SMEM (GSTG*32768 + 1024)

__global__ __launch_bounds__(256, 2)
void gemm_mma(const __nv_bfloat16* __restrict__ Ah, const __nv_bfloat16* __restrict__ Al,
              const __nv_bfloat16* __restrict__ Bh, const __nv_bfloat16* __restrict__ Bl,
              const float* __restrict__ bias,
              float* __restrict__ C, float* __restrict__ C2, float* __restrict__ C3,
              __nv_bfloat16* __restrict__ Ch, __nv_bfloat16* __restrict__ Cl,
              int M, int N, int K, int lda, int mode)
{
    extern __shared__ char dsm[];
    uint32_t raw = smem_u32(dsm);
    uint32_t s0 = (raw + 1023) & ~1023u;

    int tid = threadIdx.x, wid = tid >> 5, lane = tid & 31;
    int wm = wid & 1, wn = wid >> 1;
    long mBase = (long)blockIdx.y * 128;
    long nBase = (long)blockIdx.x * 128;
    int kOff = blockIdx.z * K;

    float acc[4][4][4];
    #pragma unroll
    for (int i = 0; i < 4; i++)
        #pragma unroll
        for (int j = 0; j < 4; j++)
            #pragma unroll
            for (int q = 0; q < 4; q++) acc[i][j][q] = 0.f;

    int lrow = tid >> 1, lkc0 = (tid & 1) * 2;
    const __nv_bfloat16* Ahp = Ah + (size_t)(mBase + lrow) * lda + kOff;
    const __nv_bfloat16* Alp = Al + (size_t)(mBase + lrow) * lda + kOff;
    const __nv_bfloat16* Bhp = Bh + (size_t)(nBase + lrow) * lda + kOff;
    const __nv_bfloat16* Blp = Bl + (size_t)(nBase + lrow) * lda + kOff;
    uint32_t sw0 = swz(lrow * 64 + lkc0 * 16);
    uint32_t sw1 = swz(lrow * 64 + (lkc0 + 1) * 16);
    const int nIt = K / 32;

    #pragma unroll 1
    for (int pf = 0; pf < 2; pf++) {
        uint32_t sb = s0 + pf * 32768;
        int k0 = pf * 32 + lkc0 * 8;
        cpa16(sb + sw0, Ahp + k0);          cpa16(sb + sw1, Ahp + k0 + 8);
        cpa16(sb + 8192 + sw0, Alp + k0);   cpa16(sb + 8192 + sw1, Alp + k0 + 8);
        cpa16(sb + 16384 + sw0, Bhp + k0);  cpa16(sb + 16384 + sw1, Bhp + k0 + 8);
        cpa16(sb + 24576 + sw0, Blp + k0);  cpa16(sb + 24576 + sw1, Blp + k0 + 8);
        cp_commit();
    }

    #pragma unroll 1
    for (int it = 0; it < nIt; ++it) {
        if (it < nIt - 1) cp_wait<1>(); else cp_wait<0>();
        __syncthreads();
        if (it + 2 < nIt) {
            uint32_t sb = s0 + ((it + 2) % GSTG) * 32768;
            int k0 = (it + 2) * 32 + lkc0 * 8;
            cpa16(sb + sw0, Ahp + k0);          cpa16(sb + sw1, Ahp + k0 + 8);
            cpa16(sb + 8192 + sw0, Alp + k0);   cpa16(sb + 8192 + sw1, Alp + k0 + 8);
            cpa16(sb + 16384 + sw0, Bhp + k0);  cpa16(sb + 16384 + sw1, Bhp + k0 + 8);
            cpa16(sb + 24576 + sw0, Blp + k0);  cpa16(sb + 24576 + sw1, Blp + k0 + 8);
            cp_commit();
        }
        uint32_t base = s0 + (it % GSTG) * 32768;
        #pragma unroll
        for (int ks = 0; ks < 2; ks++) {
            uint32_t kcol = (ks * 2 + (lane >> 4)) * 16;
            int brow = wn * 32 + (lane & 15);
            uint32_t bh[4][2], bl[4][2];
            #pragma unroll
            for (int n2 = 0; n2 < 2; n2++) {
                uint32_t r0, r1, r2, r3;
                ldsm4(r0, r1, r2, r3, base + 16384 + swz((brow + n2 * 16) * 64 + kcol));
                bh[n2*2][0] = r0; bh[n2*2][1] = r2; bh[n2*2+1][0] = r1; bh[n2*2+1][1] = r3;
                ldsm4(r0, r1, r2, r3, base + 24576 + swz((brow + n2 * 16) * 64 + kcol));
                bl[n2*2][0] = r0; bl[n2*2][1] = r2; bl[n2*2+1][0] = r1; bl[n2*2+1][1] = r3;
            }
            int arow = wm * 64 + (lane & 15);
            #pragma unroll
            for (int mt = 0; mt < 4; mt++) {
                uint32_t a[4];
                ldsm4(a[0], a[1], a[2], a[3], base + swz((arow + mt * 16) * 64 + kcol));
                #pragma unroll
                for (int nt = 0; nt < 4; nt++) mma_bf16(acc[mt][nt], a, bh[nt]);
                #pragma unroll
                for (int nt = 0; nt < 4; nt++) mma_bf16(acc[mt][nt], a, bl[nt]);
                ldsm4(a[0], a[1], a[2], a[3], base + 8192 + swz((arow + mt * 16) * 64 + kcol));
                #pragma unroll
                for (int nt = 0; nt < 4; nt++) mma_bf16(acc[mt][nt], a, bh[nt]);
            }
        }
    }

    float* dst = (blockIdx.z == 0) ? C : (blockIdx.z == 1 ? C2 : C3);
    #pragma unroll
    for (int mt = 0; mt < 4; mt++) {
        #pragma unroll
        for (int half = 0; half < 2; half++) {
            long m = mBase + wm * 64 + mt * 16 + (lane >> 2) + half * 8;
            #pragma unroll
            for (int nt = 0; nt < 4; nt++) {
                long n0 = nBase + wn * 32 + nt * 8 + (lane & 3) * 2;
                float v0 = acc[mt][nt][half * 2];
                float v1 = acc[mt][nt][half * 2 + 1];
                if (mode == 0) {
                    *(float2*)(dst + m * N + n0) = make_float2(v0, v1);
                } else {
                    v0 += __ldg(bias + n0); v1 += __ldg(bias + n0 + 1);
                    if (mode == 1) {
                        v0 = 0.5f * v0 * (1.0f + erff(v0 * 0.70710678118654752f));
                        v1 = 0.5f * v1 * (1.0f + erff(v1 * 0.70710678118654752f));
                    } else {
                        float sc = (n0 < DD) ? 0.125f : 1.0f;
                        v0 *= sc; v1 *= sc;
                    }
                    uint32_t ph, pl; pack2(v0, v1, ph, pl);
                    *(uint32_t*)(Ch + m * N + n0) = ph;
                    *(uint32_t*)(Cl + m * N + n0) = pl;
                }
            }
        }
    }
}

// ---------------- flash attention -------------------------------------------------
#define A_QH 0
#define A_QL 16384
#define A_KV 32768
#define A_MK (32768 + 98304)
#define ATTN_SMEM (131072 + 2048 + 1024)

__global__ __launch_bounds__(256, 1)
void attn_flash(const __nv_bfloat16* __restrict__ qkv_h,
                const __nv_bfloat16* __restrict__ qkv_l,
                const int* __restrict__ mask,
                __nv_bfloat16* __restrict__ ctx_h, __nv_bfloat16* __restrict__ ctx_l)
{
    extern __shared__ char dsm[];
    uint32_t raw = smem_u32(dsm);
    uint32_t s0 = (raw + 1023) & ~1023u;
    char* sm = dsm + (s0 - raw);

    int b = blockIdx.z, h = blockIdx.y, qt = blockIdx.x;
    int tid = threadIdx.x, wid = tid >> 5, lane = tid & 31;
    int q0 = b * SS + qt * 128;
    int k0g = b * SS;

    float* maskf = (float*)(sm + A_MK);
    for (int i = tid; i < SS; i += 256) maskf[i] = (float)mask[b * SS + i];

    #pragma unroll
    for (int r2 = 0; r2 < 4; r2++) {
        int i = tid + r2 * 256;
        int row = i >> 3, c = i & 7;
        uint32_t sw = swz(row * 128 + c * 16);
        size_t gq = (size_t)(q0 + row) * NQKV + h * DH + c * 8;
        cpa16(s0 + A_QH + sw, qkv_h + gq);
        cpa16(s0 + A_QL + sw, qkv_l + gq);
    }
    cp_commit();

    auto ldKV = [&](int ch, int stg) {
        uint32_t kb = s0 + A_KV + stg * 32768;
        #pragma unroll
        for (int r2 = 0; r2 < 2; r2++) {
            int i = tid + r2 * 256;
            int row = i >> 3, c = i & 7;
            uint32_t sw = swz(row * 128 + c * 16);
            size_t gk = (size_t)(k0g + ch * 64 + row) * NQKV + DD + h * DH + c * 8;
            cpa16(kb + sw,         qkv_h + gk);
            cpa16(kb + 8192 + sw,  qkv_l + gk);
            cpa16(kb + 16384 + sw, qkv_h + gk + DD);
            cpa16(kb + 24576 + sw, qkv_l + gk + DD);
        }
        cp_commit();
    };
    ldKV(0, 0);
    ldKV(1, 1);

    cp_wait<2>(); __syncthreads();

    uint32_t qh[4][4], ql[4][4];
    {
        int qr = wid * 16 + (lane & 15);
        #pragma unroll
        for (int ks = 0; ks < 4; ks++) {
            uint32_t o2 = swz(qr * 128 + (ks * 2 + (lane >> 4)) * 16);
            ldsm4(qh[ks][0], qh[ks][1], qh[ks][2], qh[ks][3], s0 + A_QH + o2);
            ldsm4(ql[ks][0], ql[ks][1], ql[ks][2], ql[ks][3], s0 + A_QL + o2);
        }
    }

    float M[2] = {-1e30f, -1e30f}, Zs[2] = {0.f, 0.f}, Zm[2] = {0.f, 0.f};
    float o[8][4];
    #pragma unroll
    for (int i = 0; i < 8; i++)
        #pragma unroll
        for (int j = 0; j < 4; j++) o[i][j] = 0.f;

    #pragma unroll 1
    for (int ch = 0; ch < 8; ch++) {
        if (ch < 7) cp_wait<1>(); else cp_wait<0>();
        __syncthreads();
        if (ch + 2 < 8) ldKV(ch + 2, (ch + 2) % 3);

        uint32_t kb = s0 + A_KV + (ch % 3) * 32768;
        float s[8][4];
        #pragma unroll
        for (int i = 0; i < 8; i++)
            #pragma unroll
            for (int j = 0; j < 4; j++) s[i][j] = 0.f;

        #pragma unroll
        for (int n4 = 0; n4 < 4; n4++) {
            int br = n4 * 16 + (lane & 15);
            #pragma unroll
            for (int ks = 0; ks < 4; ks++) {
                uint32_t kcol = (ks * 2 + (lane >> 4)) * 16;
                uint32_t r0, r1, r2, r3;
                uint32_t bh0[2], bh1[2], bl0[2], bl1[2];
                ldsm4(r0, r1, r2, r3, kb + swz(br * 128 + kcol));
                bh0[0] = r0; bh0[1] = r2; bh1[0] = r1; bh1[1] = r3;
                ldsm4(r0, r1, r2, r3, kb + 8192 + swz(br * 128 + kcol));
                bl0[0] = r0; bl0[1] = r2; bl1[0] = r1; bl1[1] = r3;
                mma_bf16(s[n4*2], qh[ks], bh0);  mma_bf16(s[n4*2+1], qh[ks], bh1);
                mma_bf16(s[n4*2], qh[ks], bl0);  mma_bf16(s[n4*2+1], qh[ks], bl1);
                mma_bf16(s[n4*2], ql[ks], bh0);  mma_bf16(s[n4*2+1], ql[ks], bh1);
            }
        }

        #pragma unroll
        for (int g = 0; g < 2; g++) {
            float mx = -1e30f;
            #pragma unroll
            for (int nt = 0; nt < 8; nt++)
                mx = fmaxf(mx, fmaxf(s[nt][2*g], s[nt][2*g+1]));
            mx = fmaxf(mx, __shfl_xor_sync(0xffffffffu, mx, 1));
            mx = fmaxf(mx, __shfl_xor_sync(0xffffffffu, mx, 2));
            float Mn = fmaxf(M[g], mx);
            float fac = __expf(M[g] - Mn);
            float zc = 0.f, zmc = 0.f;
            #pragma unroll
            for (int nt = 0; nt < 8; nt++) {
                #pragma unroll
                for (int e = 0; e < 2; e++) {
                    int col = ch * 64 + nt * 8 + (lane & 3) * 2 + e;
                    float ex = __expf(s[nt][2*g+e] - Mn);
                    float mm = maskf[col];
                    zc += ex; zmc += ex * mm;
                    s[nt][2*g+e] = ex * mm;
                }
            }
            zc += __shfl_xor_sync(0xffffffffu, zc, 1);
            zc += __shfl_xor_sync(0xffffffffu, zc, 2);
            zmc += __shfl_xor_sync(0xffffffffu, zmc, 1);
            zmc += __shfl_xor_sync(0xffffffffu, zmc, 2);
            Zs[g] = Zs[g] * fac + zc;
            Zm[g] = Zm[g] * fac + zmc;
            M[g] = Mn;
            #pragma unroll
            for (int nt = 0; nt < 8; nt++) { o[nt][2*g] *= fac; o[nt][2*g+1] *= fac; }
        }

        uint32_t ah[4][4], al[4][4];
        #pragma unroll
        for (int kt = 0; kt < 4; kt++) {
            pack2(s[2*kt][0],   s[2*kt][1],   ah[kt][0], al[kt][0]);
            pack2(s[2*kt][2],   s[2*kt][3],   ah[kt][1], al[kt][1]);
            pack2(s[2*kt+1][0], s[2*kt+1][1], ah[kt][2], al[kt][2]);
            pack2(s[2*kt+1][2], s[2*kt+1][3], ah[kt][3], al[kt][3]);
        }

        uint32_t vb = kb + 16384;
        #pragma unroll
        for (int n4 = 0; n4 < 4; n4++) {
            #pragma unroll
            for (int kt = 0; kt < 4; kt++) {
                uint32_t addr = swz((kt * 16 + (lane & 15)) * 128 + n4 * 32 + (lane >> 4) * 16);
                uint32_t r0, r1, r2, r3;
                uint32_t bh0[2], bh1[2], bl0[2], bl1[2];
                ldsm4t(r0, r1, r2, r3, vb + addr);
                bh0[0] = r0; bh0[1] = r1; bh1[0] = r2; bh1[1] = r3;
                ldsm4t(r0, r1, r2, r3, vb + 8192 + addr);
                bl0[0] = r0; bl0[1] = r1; bl1[0] = r2; bl1[1] = r3;
                mma_bf16(o[n4*2], ah[kt], bh0);  mma_bf16(o[n4*2+1], ah[kt], bh1);
                mma_bf16(o[n4*2], ah[kt], bl0);  mma_bf16(o[n4*2+1], ah[kt], bl1);
                mma_bf16(o[n4*2], al[kt], bh0);  mma_bf16(o[n4*2+1], al[kt], bh1);
            }
        }
    }

    #pragma unroll
    for (int g = 0; g < 2; g++) {
        float den = fmaxf(Zm[g], 1e-9f * Zs[g]);
        float rcp = 1.0f / den;
        size_t row = q0 + wid * 16 + (lane >> 2) + g * 8;
        #pragma unroll
        for (int nt = 0; nt < 8; nt++) {
            int col = h * DH + nt * 8 + (lane & 3) * 2;
            uint32_t ph, pl;
            pack2(o[nt][2*g] * rcp, o[nt][2*g+1] * rcp, ph, pl);
            *(uint32_t*)(ctx_h + row * DD + col) = ph;
            *(uint32_t*)(ctx_l + row * DD + col) = pl;
        }
    }
}

// ---------------- pool + normalize ------------------------------------------------
__global__ void pool_kernel(const float* __restrict__ h, const int* __restrict__ mask,
                            float* __restrict__ out)
{
    __shared__ float sent[DD];
    __shared__ float red[32];
    int b = blockIdx.x, tid = threadIdx.x;
    float ms = 0.f;
    for (int s = tid; s < SS; s += 256) ms += (float)mask[b * SS + s];
    ms = blockReduceSum(ms, red);
    float inv = 1.0f / fmaxf(ms, 1e-6f);
    for (int d = tid; d < DD; d += 256) {
        float a = 0.f;
        const float* hp = h + ((size_t)b * SS) * DD + d;
        const int* mp = mask + b * SS;
        for (int s = 0; s < SS; s++) a += hp[(size_t)s * DD] * (float)mp[s];
        sent[d] = a * inv;
    }
    __syncthreads();
    float sq = 0.f;
    for (int d = tid; d < DD; d += 256) sq += sent[d] * sent[d];
    sq = blockReduceSum(sq, red);
    float rn = 1.0f / fmaxf(sqrtf(sq), 1e-12f);
    for (int d = tid; d < DD; d += 256) out[b * DD + d] = sent[d] * rn;
}

// ---------------- launch -----------------------------------------------------------
extern "C" void kernel_launch(void* const* d_in, const int* in_sizes, int n_in,
                              void* d_out, int out_size)
{
    const int*   input_ids = (const int*)  d_in[0];
    const int*   amask     = (const int*)  d_in[1];
    const float* word_emb  = (const float*)d_in[2];
    const float* pos_emb   = (const float*)d_in[3];
    const float* type_emb  = (const float*)d_in[4];
    const float* emb_g     = (const float*)d_in[5];
    const float* emb_b     = (const float*)d_in[6];
    const float* Wq = (const float*)d_in[7];  const float* bq = (const float*)d_in[8];
    const float* Wk = (const float*)d_in[9];  const float* bk = (const float*)d_in[10];
    const float* Wv = (const float*)d_in[11]; const float* bv = (const float*)d_in[12];
    const float* Wo = (const float*)d_in[13]; const float* bo = (const float*)d_in[14];
    const float* ln1g = (const float*)d_in[15]; const float* ln1b = (const float*)d_in[16];
    const float* Wi = (const float*)d_in[17]; const float* bi = (const float*)d_in[18];
    const float* Wf = (const float*)d_in[19]; const float* bf = (const float*)d_in[20];
    const float* ln2g = (const float*)d_in[21]; const float* ln2b = (const float*)d_in[22];
    float* out = (float*)d_out;

    float *p_h, *p_t1, *p_t2, *p_t3, *p_bqkv;
    __nv_bfloat16 *p_hh, *p_hl, *p_qh, *p_ql, *p_ch, *p_cl, *p_fh, *p_fl;
    __nv_bfloat16 *wqkv_h, *wqkv_l, *wo_h, *wo_l, *wi_h, *wi_l, *wf_h, *wf_l;
    cudaGetSymbolAddress((void**)&p_h,  g_h);
    cudaGetSymbolAddress((void**)&p_t1, g_t1);
    cudaGetSymbolAddress((void**)&p_t2, g_t2);
    cudaGetSymbolAddress((void**)&p_t3, g_t3);
    cudaGetSymbolAddress((void**)&p_bqkv, g_bqkv);
    cudaGetSymbolAddress((void**)&p_hh, g_h_hi);
    cudaGetSymbolAddress((void**)&p_hl, g_h_lo);
    cudaGetSymbolAddress((void**)&p_qh, g_qkv_h);
    cudaGetSymbolAddress((void**)&p_ql, g_qkv_l);
    cudaGetSymbolAddress((void**)&p_ch, g_ctx_hi);
    cudaGetSymbolAddress((void**)&p_cl, g_ctx_lo);
    cudaGetSymbolAddress((void**)&p_fh, g_ff_hi);
    cudaGetSymbolAddress((void**)&p_fl, g_ff_lo);
    cudaGetSymbolAddress((void**)&wqkv_h, g_Wqkv_h); cudaGetSymbolAddress((void**)&wqkv_l, g_Wqkv_l);
    cudaGetSymbolAddress((void**)&wo_h, g_WoT_h);    cudaGetSymbolAddress((void**)&wo_l, g_WoT_l);
    cudaGetSymbolAddress((void**)&wi_h, g_WiT_h);    cudaGetSymbolAddress((void**)&wi_l, g_WiT_l);
    cudaGetSymbolAddress((void**)&wf_h, g_WfT_h);    cudaGetSymbolAddress((void**)&wf_l, g_WfT_l);

    cudaFuncSetAttribute(gemm_mma, cudaFuncAttributeMaxDynamicSharedMemorySize, GEMM_SMEM);
    cudaFuncSetAttribute(attn_flash, cudaFuncAttributeMaxDynamicSharedMemorySize, ATTN_SMEM);

    trans_all<<<LL * 6912, dim3(32, 8)>>>(Wq, Wk, Wv, Wo, Wi, Wf);
    fuse_bias<<<(LL * NQKV + 255) / 256, 256>>>(bq, bk, bv);
    embed_ln_kernel<<<MTOK, 256>>>(input_ids, word_emb, pos_emb, type_emb,
                                   emb_g, emb_b, p_h, p_hh, p_hl);

    dim3 gQKV(NQKV / 128, MTOK / 128, 1);
    dim3 gSK2(DD   / 128, MTOK / 128, 2);   // Wo: split-K=2 (same chunk count, 1 fewer partial)
    dim3 gSK3(DD   / 128, MTOK / 128, 3);   // Wf: split-K=3
    dim3 gFF (FFD  / 128, MTOK / 128, 1);

    for (int l = 0; l < LL; l++) {
        size_t wdd = (size_t)l * DD * DD;
        size_t wdf = (size_t)l * DD * FFD;
        size_t wqk = (size_t)l * NQKV * DD;

        gemm_mma<<<gQKV, 256, GEMM_SMEM>>>(p_hh, p_hl, wqkv_h + wqk, wqkv_l + wqk,
                                           p_bqkv + l * NQKV, nullptr, nullptr, nullptr,
                                           p_qh, p_ql, MTOK, NQKV, DD, DD, 3);

        attn_flash<<<dim3(4, HH, BB), 256, ATTN_SMEM>>>(p_qh, p_ql, amask, p_ch, p_cl);

        gemm_mma<<<gSK2, 256, GEMM_SMEM>>>(p_ch, p_cl, wo_h + wdd, wo_l + wdd,
                                           nullptr, p_t1, p_t2, p_t3, nullptr, nullptr,
                                           MTOK, DD, DD / 2, DD, 0);
        ln_sum_kernel<<<MTOK, 256>>>(p_t1, p_t2, p_t3, 2, bo + l * DD, p_h,
                                     ln1g + l * DD, ln1b + l * DD, p_h, p_hh, p_hl);

        gemm_mma<<<gFF, 256, GEMM_SMEM>>>(p_hh, p_hl, wi_h + wdf, wi_l + wdf,
                                          bi + l * FFD, nullptr, nullptr, nullptr,
                                          p_fh, p_fl, MTOK, FFD, DD, DD, 1);

        gemm_mma<<<gSK3, 256, GEMM_SMEM>>>(p_fh, p_fl, wf_h + wdf, wf_l + wdf,
                                           nullptr, p_t1, p_t2, p_t3, nullptr, nullptr,
                                           MTOK, DD, FFD / 3, FFD, 0);
        ln_sum_kernel<<<MTOK, 256>>>(p_t1, p_t2, p_t3, 3, bf + l * DD, p_h,
                                     ln2g + l * DD, ln2b + l * DD, p_h, p_hh, p_hl);
    }

    pool_kernel<<<BB, 256>>>(p_h, amask, out);
}

// round 14
// speedup vs baseline: 1.7900x; 1.0175x over previous
#include <cuda_runtime.h>
#include <cuda_bf16.h>
#include <math.h>
#include <stdint.h>

#define BB 8
#define SS 512
#define DD 768
#define HH 12
#define DH 64
#define LL 12
#define FFD 3072
#define MTOK (BB*SS)
#define NQKV 2304

__device__ __align__(256) float g_h  [MTOK*DD];
__device__ __align__(256) float g_t1 [MTOK*DD];
__device__ __align__(256) float g_t2 [MTOK*DD];
__device__ __align__(256) float g_t3 [MTOK*DD];

__device__ __align__(256) __nv_bfloat16 g_h_hi [MTOK*DD];
__device__ __align__(256) __nv_bfloat16 g_h_lo [MTOK*DD];
__device__ __align__(256) __nv_bfloat16 g_qkv_h[MTOK*NQKV];
__device__ __align__(256) __nv_bfloat16 g_qkv_l[MTOK*NQKV];
__device__ __align__(256) __nv_bfloat16 g_ctx_hi[MTOK*DD];
__device__ __align__(256) __nv_bfloat16 g_ctx_lo[MTOK*DD];
__device__ __align__(256) __nv_bfloat16 g_ff_hi[MTOK*FFD];
__device__ __align__(256) __nv_bfloat16 g_ff_lo[MTOK*FFD];

__device__ __align__(256) __nv_bfloat16 g_Wqkv_h[LL*NQKV*DD];
__device__ __align__(256) __nv_bfloat16 g_Wqkv_l[LL*NQKV*DD];
__device__ __align__(256) __nv_bfloat16 g_WoT_h[LL*DD*DD];
__device__ __align__(256) __nv_bfloat16 g_WoT_l[LL*DD*DD];
__device__ __align__(256) __nv_bfloat16 g_WiT_h[LL*DD*FFD];
__device__ __align__(256) __nv_bfloat16 g_WiT_l[LL*DD*FFD];
__device__ __align__(256) __nv_bfloat16 g_WfT_h[LL*DD*FFD];
__device__ __align__(256) __nv_bfloat16 g_WfT_l[LL*DD*FFD];
__device__ __align__(256) float g_bqkv[LL*NQKV];

// ---------------- helpers ------------------------------------------------------
__device__ __forceinline__ uint32_t smem_u32(const void* p) {
    uint32_t a;
    asm("{ .reg .u64 t; cvta.to.shared.u64 t, %1; cvt.u32.u64 %0, t; }" : "=r"(a) : "l"(p));
    return a;
}
__device__ __forceinline__ uint32_t swz(uint32_t o) { return o ^ ((o >> 3) & 0x70); }
__device__ __forceinline__ void cpa16(uint32_t saddr, const void* g) {
    asm volatile("cp.async.cg.shared.global [%0], [%1], 16;" :: "r"(saddr), "l"(g));
}
__device__ __forceinline__ void cp_commit() {
    asm volatile("cp.async.commit_group;" ::: "memory");
}
template <int N>
__device__ __forceinline__ void cp_wait() {
    asm volatile("cp.async.wait_group %0;" :: "n"(N) : "memory");
}
__device__ __forceinline__ void ldsm4(uint32_t& r0, uint32_t& r1, uint32_t& r2, uint32_t& r3,
                                      uint32_t addr) {
    asm volatile("ldmatrix.sync.aligned.m8n8.x4.shared.b16 {%0,%1,%2,%3}, [%4];"
                 : "=r"(r0), "=r"(r1), "=r"(r2), "=r"(r3) : "r"(addr));
}
__device__ __forceinline__ void ldsm4t(uint32_t& r0, uint32_t& r1, uint32_t& r2, uint32_t& r3,
                                       uint32_t addr) {
    asm volatile("ldmatrix.sync.aligned.m8n8.x4.trans.shared.b16 {%0,%1,%2,%3}, [%4];"
                 : "=r"(r0), "=r"(r1), "=r"(r2), "=r"(r3) : "r"(addr));
}
__device__ __forceinline__ void mma_bf16(float* d, const uint32_t* a, const uint32_t* b) {
    asm volatile("mma.sync.aligned.m16n8k16.row.col.f32.bf16.bf16.f32 "
                 "{%0,%1,%2,%3}, {%4,%5,%6,%7}, {%8,%9}, {%0,%1,%2,%3};"
                 : "+f"(d[0]), "+f"(d[1]), "+f"(d[2]), "+f"(d[3])
                 : "r"(a[0]), "r"(a[1]), "r"(a[2]), "r"(a[3]), "r"(b[0]), "r"(b[1]));
}
__device__ __forceinline__ void split_bf16(float x, __nv_bfloat16& hi, __nv_bfloat16& lo) {
    hi = __float2bfloat16(x);
    lo = __float2bfloat16(x - __bfloat162float(hi));
}
__device__ __forceinline__ void pack2(float a, float b, uint32_t& ph, uint32_t& pl) {
    __nv_bfloat16 ha, la, hb, lb;
    split_bf16(a, ha, la); split_bf16(b, hb, lb);
    __nv_bfloat162 th(ha, hb), tl(la, lb);
    ph = *(uint32_t*)&th; pl = *(uint32_t*)&tl;
}
__device__ __forceinline__ float blockReduceSum(float v, float* red) {
    int lane = threadIdx.x & 31, w = threadIdx.x >> 5;
    #pragma unroll
    for (int o = 16; o; o >>= 1) v += __shfl_xor_sync(0xffffffffu, v, o);
    if (lane == 0) red[w] = v;
    __syncthreads();
    float t = (threadIdx.x < (blockDim.x >> 5)) ? red[threadIdx.x] : 0.f;
    if (w == 0) {
        #pragma unroll
        for (int o = 16; o; o >>= 1) t += __shfl_xor_sync(0xffffffffu, t, o);
        if (lane == 0) red[0] = t;
    }
    __syncthreads();
    return red[0];
}

// ---------------- weight prep ------------------------------------------------------
__global__ void trans_all(const float* __restrict__ Wq, const float* __restrict__ Wk,
                          const float* __restrict__ Wv, const float* __restrict__ Wo,
                          const float* __restrict__ Wi, const float* __restrict__ Wf)
{
    __shared__ float tsm[32][33];
    int t = blockIdx.x;
    int l = t / 6912, r = t % 6912;
    const float* src; __nv_bfloat16 *dh, *dl;
    int K, N, rowoff, nx, ky;
    if (r < 1728) {
        int w = r / 576, q2 = r % 576;
        src = (w == 0 ? Wq : w == 1 ? Wk : Wv) + (size_t)l * DD * DD;
        dh = g_Wqkv_h + (size_t)l * NQKV * DD; dl = g_Wqkv_l + (size_t)l * NQKV * DD;
        K = DD; N = DD; rowoff = w * DD; ky = q2 / 24; nx = q2 % 24;
    } else if (r < 2304) {
        int q2 = r - 1728;
        src = Wo + (size_t)l * DD * DD;
        dh = g_WoT_h + (size_t)l * DD * DD; dl = g_WoT_l + (size_t)l * DD * DD;
        K = DD; N = DD; rowoff = 0; ky = q2 / 24; nx = q2 % 24;
    } else if (r < 4608) {
        int q2 = r - 2304;
        src = Wi + (size_t)l * DD * FFD;
        dh = g_WiT_h + (size_t)l * DD * FFD; dl = g_WiT_l + (size_t)l * DD * FFD;
        K = DD; N = FFD; rowoff = 0; ky = q2 / 96; nx = q2 % 96;
    } else {
        int q2 = r - 4608;
        src = Wf + (size_t)l * FFD * DD;
        dh = g_WfT_h + (size_t)l * DD * FFD; dl = g_WfT_l + (size_t)l * DD * FFD;
        K = FFD; N = DD; rowoff = 0; ky = q2 / 24; nx = q2 % 24;
    }
    int n0 = nx * 32, k0 = ky * 32;
    int tx = threadIdx.x;
    for (int i = threadIdx.y; i < 32; i += 8)
        tsm[i][tx] = src[(size_t)(k0 + i) * N + n0 + tx];
    __syncthreads();
    for (int i = threadIdx.y; i < 32; i += 8) {
        float v = tsm[tx][i];
        __nv_bfloat16 hi, lo; split_bf16(v, hi, lo);
        size_t o = (size_t)(rowoff + n0 + i) * K + k0 + tx;
        dh[o] = hi; dl[o] = lo;
    }
}

__global__ void fuse_bias(const float* __restrict__ bq, const float* __restrict__ bk,
                          const float* __restrict__ bv)
{
    int i = blockIdx.x * 256 + threadIdx.x;
    if (i >= LL * NQKV) return;
    int l = i / NQKV, n = i % NQKV;
    g_bqkv[i] = (n < DD) ? bq[l * DD + n]
              : (n < 2 * DD) ? bk[l * DD + n - DD]
                             : bv[l * DD + n - 2 * DD];
}

// ---------------- embedding LN (384 thr, float2-vectorized) -----------------------
__global__ __launch_bounds__(384)
void embed_ln_kernel(const int* __restrict__ ids, const float* __restrict__ we,
                     const float* __restrict__ pe, const float* __restrict__ te,
                     const float* __restrict__ gam, const float* __restrict__ bet,
                     float* __restrict__ out,
                     __nv_bfloat16* __restrict__ oh, __nv_bfloat16* __restrict__ ol)
{
    __shared__ float red[32];
    int tok = blockIdx.x, s = tok & (SS - 1), id = ids[tok], tid = threadIdx.x;
    int d = tid * 2;
    float2 w2 = *(const float2*)(we + (size_t)id * DD + d);
    float2 p2 = *(const float2*)(pe + (size_t)s * DD + d);
    float2 t2 = *(const float2*)(te + d);
    float x0 = w2.x + p2.x + t2.x;
    float x1 = w2.y + p2.y + t2.y;
    float mu = blockReduceSum(x0 + x1, red) * (1.0f / DD);
    float d0 = x0 - mu, d1 = x1 - mu;
    float var = blockReduceSum(d0 * d0 + d1 * d1, red) * (1.0f / DD);
    float r = rsqrtf(var + 1e-12f);
    float2 g2 = *(const float2*)(gam + d);
    float2 b2 = *(const float2*)(bet + d);
    float o0 = d0 * r * g2.x + b2.x;
    float o1 = d1 * r * g2.y + b2.y;
    size_t ro = (size_t)tok * DD + d;
    *(float2*)(out + ro) = make_float2(o0, o1);
    uint32_t ph, pl; pack2(o0, o1, ph, pl);
    *(uint32_t*)(oh + ro) = ph;
    *(uint32_t*)(ol + ro) = pl;
}

// ---------------- LN over (p0+p1+p2+bias+res), 384 thr, vectorized ----------------
__global__ __launch_bounds__(384)
void ln_sum3_kernel(const float* __restrict__ p0, const float* __restrict__ p1,
                    const float* __restrict__ p2,
                    const float* __restrict__ bias, const float* __restrict__ res,
                    const float* __restrict__ gam, const float* __restrict__ bet,
                    float* __restrict__ out,
                    __nv_bfloat16* __restrict__ oh, __nv_bfloat16* __restrict__ ol)
{
    __shared__ float red[32];
    int row = blockIdx.x, tid = threadIdx.x;
    int d = tid * 2;
    size_t ro = (size_t)row * DD + d;
    float2 a2 = *(const float2*)(p0 + ro);
    float2 c2 = *(const float2*)(p1 + ro);
    float2 e2 = *(const float2*)(p2 + ro);
    float2 r2 = *(const float2*)(res + ro);
    float2 bb = *(const float2*)(bias + d);
    float x0 = a2.x + c2.x + e2.x + r2.x + bb.x;
    float x1 = a2.y + c2.y + e2.y + r2.y + bb.y;
    float mu = blockReduceSum(x0 + x1, red) * (1.0f / DD);
    float d0 = x0 - mu, d1 = x1 - mu;
    float var = blockReduceSum(d0 * d0 + d1 * d1, red) * (1.0f / DD);
    float r = rsqrtf(var + 1e-12f);
    float2 g2 = *(const float2*)(gam + d);
    float2 be2 = *(const float2*)(bet + d);
    float o0 = d0 * r * g2.x + be2.x;
    float o1 = d1 * r * g2.y + be2.y;
    *(float2*)(out + ro) = make_float2(o0, o1);
    uint32_t ph, pl; pack2(o0, o1, ph, pl);
    *(uint32_t*)(oh + ro) = ph;
    *(uint32_t*)(ol + ro) = pl;
}

// ---------------- GEMM (R10 exact) -------------------------------------------------
#define GSTG 3
#define GEMM_SMEM (GSTG*32768 + 1024)

__global__ __launch_bounds__(256, 2)
void gemm_mma(const __nv_bfloat16* __restrict__ Ah, const __nv_bfloat16* __restrict__ Al,
              const __nv_bfloat16* __restrict__ Bh, const __nv_bfloat16* __restrict__ Bl,
              const float* __restrict__ bias,
              float* __restrict__ C, float* __restrict__ C2, float* __restrict__ C3,
              __nv_bfloat16* __restrict__ Ch, __nv_bfloat16* __restrict__ Cl,
              int M, int N, int K, int lda, int mode)
{
    extern __shared__ char dsm[];
    uint32_t raw = smem_u32(dsm);
    uint32_t s0 = (raw + 1023) & ~1023u;

    int tid = threadIdx.x, wid = tid >> 5, lane = tid & 31;
    int wm = wid & 1, wn = wid >> 1;
    long mBase = (long)blockIdx.y * 128;
    long nBase = (long)blockIdx.x * 128;
    int kOff = blockIdx.z * K;

    float acc[4][4][4];
    #pragma unroll
    for (int i = 0; i < 4; i++)
        #pragma unroll
        for (int j = 0; j < 4; j++)
            #pragma unroll
            for (int q = 0; q < 4; q++) acc[i][j][q] = 0.f;

    int lrow = tid >> 1, lkc0 = (tid & 1) * 2;
    const __nv_bfloat16* Ahp = Ah + (size_t)(mBase + lrow) * lda + kOff;
    const __nv_bfloat16* Alp = Al + (size_t)(mBase + lrow) * lda + kOff;
    const __nv_bfloat16* Bhp = Bh + (size_t)(nBase + lrow) * lda + kOff;
    const __nv_bfloat16* Blp = Bl + (size_t)(nBase + lrow) * lda + kOff;
    uint32_t sw0 = swz(lrow * 64 + lkc0 * 16);
    uint32_t sw1 = swz(lrow * 64 + (lkc0 + 1) * 16);
    const int nIt = K / 32;

    #pragma unroll 1
    for (int pf = 0; pf < 2; pf++) {
        uint32_t sb = s0 + pf * 32768;
        int k0 = pf * 32 + lkc0 * 8;
        cpa16(sb + sw0, Ahp + k0);          cpa16(sb + sw1, Ahp + k0 + 8);
        cpa16(sb + 8192 + sw0, Alp + k0);   cpa16(sb + 8192 + sw1, Alp + k0 + 8);
        cpa16(sb + 16384 + sw0, Bhp + k0);  cpa16(sb + 16384 + sw1, Bhp + k0 + 8);
        cpa16(sb + 24576 + sw0, Blp + k0);  cpa16(sb + 24576 + sw1, Blp + k0 + 8);
        cp_commit();
    }

    #pragma unroll 1
    for (int it = 0; it < nIt; ++it) {
        if (it < nIt - 1) cp_wait<1>(); else cp_wait<0>();
        __syncthreads();
        if (it + 2 < nIt) {
            uint32_t sb = s0 + ((it + 2) % GSTG) * 32768;
            int k0 = (it + 2) * 32 + lkc0 * 8;
            cpa16(sb + sw0, Ahp + k0);          cpa16(sb + sw1, Ahp + k0 + 8);
            cpa16(sb + 8192 + sw0, Alp + k0);   cpa16(sb + 8192 + sw1, Alp + k0 + 8);
            cpa16(sb + 16384 + sw0, Bhp + k0);  cpa16(sb + 16384 + sw1, Bhp + k0 + 8);
            cpa16(sb + 24576 + sw0, Blp + k0);  cpa16(sb + 24576 + sw1, Blp + k0 + 8);
            cp_commit();
        }
        uint32_t base = s0 + (it % GSTG) * 32768;
        #pragma unroll
        for (int ks = 0; ks < 2; ks++) {
            uint32_t kcol = (ks * 2 + (lane >> 4)) * 16;
            int brow = wn * 32 + (lane & 15);
            uint32_t bh[4][2], bl[4][2];
            #pragma unroll
            for (int n2 = 0; n2 < 2; n2++) {
                uint32_t r0, r1, r2, r3;
                ldsm4(r0, r1, r2, r3, base + 16384 + swz((brow + n2 * 16) * 64 + kcol));
                bh[n2*2][0] = r0; bh[n2*2][1] = r2; bh[n2*2+1][0] = r1; bh[n2*2+1][1] = r3;
                ldsm4(r0, r1, r2, r3, base + 24576 + swz((brow + n2 * 16) * 64 + kcol));
                bl[n2*2][0] = r0; bl[n2*2][1] = r2; bl[n2*2+1][0] = r1; bl[n2*2+1][1] = r3;
            }
            int arow = wm * 64 + (lane & 15);
            #pragma unroll
            for (int mt = 0; mt < 4; mt++) {
                uint32_t a[4];
                ldsm4(a[0], a[1], a[2], a[3], base + swz((arow + mt * 16) * 64 + kcol));
                #pragma unroll
                for (int nt = 0; nt < 4; nt++) mma_bf16(acc[mt][nt], a, bh[nt]);
                #pragma unroll
                for (int nt = 0; nt < 4; nt++) mma_bf16(acc[mt][nt], a, bl[nt]);
                ldsm4(a[0], a[1], a[2], a[3], base + 8192 + swz((arow + mt * 16) * 64 + kcol));
                #pragma unroll
                for (int nt = 0; nt < 4; nt++) mma_bf16(acc[mt][nt], a, bh[nt]);
            }
        }
    }

    float* dst = (blockIdx.z == 0) ? C : (blockIdx.z == 1 ? C2 : C3);
    #pragma unroll
    for (int mt = 0; mt < 4; mt++) {
        #pragma unroll
        for (int half = 0; half < 2; half++) {
            long m = mBase + wm * 64 + mt * 16 + (lane >> 2) + half * 8;
            #pragma unroll
            for (int nt = 0; nt < 4; nt++) {
                long n0 = nBase + wn * 32 + nt * 8 + (lane & 3) * 2;
                float v0 = acc[mt][nt][half * 2];
                float v1 = acc[mt][nt][half * 2 + 1];
                if (mode == 0) {
                    *(float2*)(dst + m * N + n0) = make_float2(v0, v1);
                } else {
                    v0 += __ldg(bias + n0); v1 += __ldg(bias + n0 + 1);
                    if (mode == 1) {
                        v0 = 0.5f * v0 * (1.0f + erff(v0 * 0.70710678118654752f));
                        v1 = 0.5f * v1 * (1.0f + erff(v1 * 0.70710678118654752f));
                    } else {
                        float sc = (n0 < DD) ? 0.125f : 1.0f;
                        v0 *= sc; v1 *= sc;
                    }
                    uint32_t ph, pl; pack2(v0, v1, ph, pl);
                    *(uint32_t*)(Ch + m * N + n0) = ph;
                    *(uint32_t*)(Cl + m * N + n0) = pl;
                }
            }
        }
    }
}

// ---------------- flash attention (R10 exact) ----------------------------------------
#define A_QH 0
#define A_QL 16384
#define A_KV 32768
#define A_MK (32768 + 98304)
#define ATTN_SMEM (131072 + 2048 + 1024)

__global__ __launch_bounds__(256, 1)
void attn_flash(const __nv_bfloat16* __restrict__ qkv_h,
                const __nv_bfloat16* __restrict__ qkv_l,
                const int* __restrict__ mask,
                __nv_bfloat16* __restrict__ ctx_h, __nv_bfloat16* __restrict__ ctx_l)
{
    extern __shared__ char dsm[];
    uint32_t raw = smem_u32(dsm);
    uint32_t s0 = (raw + 1023) & ~1023u;
    char* sm = dsm + (s0 - raw);

    int b = blockIdx.z, h = blockIdx.y, qt = blockIdx.x;
    int tid = threadIdx.x, wid = tid >> 5, lane = tid & 31;
    int q0 = b * SS + qt * 128;
    int k0g = b * SS;

    float* maskf = (float*)(sm + A_MK);
    for (int i = tid; i < SS; i += 256) maskf[i] = (float)mask[b * SS + i];

    #pragma unroll
    for (int r2 = 0; r2 < 4; r2++) {
        int i = tid + r2 * 256;
        int row = i >> 3, c = i & 7;
        uint32_t sw = swz(row * 128 + c * 16);
        size_t gq = (size_t)(q0 + row) * NQKV + h * DH + c * 8;
        cpa16(s0 + A_QH + sw, qkv_h + gq);
        cpa16(s0 + A_QL + sw, qkv_l + gq);
    }
    cp_commit();

    auto ldKV = [&](int ch, int stg) {
        uint32_t kb = s0 + A_KV + stg * 32768;
        #pragma unroll
        for (int r2 = 0; r2 < 2; r2++) {
            int i = tid + r2 * 256;
            int row = i >> 3, c = i & 7;
            uint32_t sw = swz(row * 128 + c * 16);
            size_t gk = (size_t)(k0g + ch * 64 + row) * NQKV + DD + h * DH + c * 8;
            cpa16(kb + sw,         qkv_h + gk);
            cpa16(kb + 8192 + sw,  qkv_l + gk);
            cpa16(kb + 16384 + sw, qkv_h + gk + DD);
            cpa16(kb + 24576 + sw, qkv_l + gk + DD);
        }
        cp_commit();
    };
    ldKV(0, 0);
    ldKV(1, 1);

    cp_wait<2>(); __syncthreads();

    uint32_t qh[4][4], ql[4][4];
    {
        int qr = wid * 16 + (lane & 15);
        #pragma unroll
        for (int ks = 0; ks < 4; ks++) {
            uint32_t o2 = swz(qr * 128 + (ks * 2 + (lane >> 4)) * 16);
            ldsm4(qh[ks][0], qh[ks][1], qh[ks][2], qh[ks][3], s0 + A_QH + o2);
            ldsm4(ql[ks][0], ql[ks][1], ql[ks][2], ql[ks][3], s0 + A_QL + o2);
        }
    }

    float M[2] = {-1e30f, -1e30f}, Zs[2] = {0.f, 0.f}, Zm[2] = {0.f, 0.f};
    float o[8][4];
    #pragma unroll
    for (int i = 0; i < 8; i++)
        #pragma unroll
        for (int j = 0; j < 4; j++) o[i][j] = 0.f;

    #pragma unroll 1
    for (int ch = 0; ch < 8; ch++) {
        if (ch < 7) cp_wait<1>(); else cp_wait<0>();
        __syncthreads();
        if (ch + 2 < 8) ldKV(ch + 2, (ch + 2) % 3);

        uint32_t kb = s0 + A_KV + (ch % 3) * 32768;
        float s[8][4];
        #pragma unroll
        for (int i = 0; i < 8; i++)
            #pragma unroll
            for (int j = 0; j < 4; j++) s[i][j] = 0.f;

        #pragma unroll
        for (int n4 = 0; n4 < 4; n4++) {
            int br = n4 * 16 + (lane & 15);
            #pragma unroll
            for (int ks = 0; ks < 4; ks++) {
                uint32_t kcol = (ks * 2 + (lane >> 4)) * 16;
                uint32_t r0, r1, r2, r3;
                uint32_t bh0[2], bh1[2], bl0[2], bl1[2];
                ldsm4(r0, r1, r2, r3, kb + swz(br * 128 + kcol));
                bh0[0] = r0; bh0[1] = r2; bh1[0] = r1; bh1[1] = r3;
                ldsm4(r0, r1, r2, r3, kb + 8192 + swz(br * 128 + kcol));
                bl0[0] = r0; bl0[1] = r2; bl1[0] = r1; bl1[1] = r3;
                mma_bf16(s[n4*2], qh[ks], bh0);  mma_bf16(s[n4*2+1], qh[ks], bh1);
                mma_bf16(s[n4*2], qh[ks], bl0);  mma_bf16(s[n4*2+1], qh[ks], bl1);
                mma_bf16(s[n4*2], ql[ks], bh0);  mma_bf16(s[n4*2+1], ql[ks], bh1);
            }
        }

        #pragma unroll
        for (int g = 0; g < 2; g++) {
            float mx = -1e30f;
            #pragma unroll
            for (int nt = 0; nt < 8; nt++)
                mx = fmaxf(mx, fmaxf(s[nt][2*g], s[nt][2*g+1]));
            mx = fmaxf(mx, __shfl_xor_sync(0xffffffffu, mx, 1));
            mx = fmaxf(mx, __shfl_xor_sync(0xffffffffu, mx, 2));
            float Mn = fmaxf(M[g], mx);
            float fac = __expf(M[g] - Mn);
            float zc = 0.f, zmc = 0.f;
            #pragma unroll
            for (int nt = 0; nt < 8; nt++) {
                #pragma unroll
                for (int e = 0; e < 2; e++) {
                    int col = ch * 64 + nt * 8 + (lane & 3) * 2 + e;
                    float ex = __expf(s[nt][2*g+e] - Mn);
                    float mm = maskf[col];
                    zc += ex; zmc += ex * mm;
                    s[nt][2*g+e] = ex * mm;
                }
            }
            zc += __shfl_xor_sync(0xffffffffu, zc, 1);
            zc += __shfl_xor_sync(0xffffffffu, zc, 2);
            zmc += __shfl_xor_sync(0xffffffffu, zmc, 1);
            zmc += __shfl_xor_sync(0xffffffffu, zmc, 2);
            Zs[g] = Zs[g] * fac + zc;
            Zm[g] = Zm[g] * fac + zmc;
            M[g] = Mn;
            #pragma unroll
            for (int nt = 0; nt < 8; nt++) { o[nt][2*g] *= fac; o[nt][2*g+1] *= fac; }
        }

        uint32_t ah[4][4], al[4][4];
        #pragma unroll
        for (int kt = 0; kt < 4; kt++) {
            pack2(s[2*kt][0],   s[2*kt][1],   ah[kt][0], al[kt][0]);
            pack2(s[2*kt][2],   s[2*kt][3],   ah[kt][1], al[kt][1]);
            pack2(s[2*kt+1][0], s[2*kt+1][1], ah[kt][2], al[kt][2]);
            pack2(s[2*kt+1][2], s[2*kt+1][3], ah[kt][3], al[kt][3]);
        }

        uint32_t vb = kb + 16384;
        #pragma unroll
        for (int n4 = 0; n4 < 4; n4++) {
            #pragma unroll
            for (int kt = 0; kt < 4; kt++) {
                uint32_t addr = swz((kt * 16 + (lane & 15)) * 128 + n4 * 32 + (lane >> 4) * 16);
                uint32_t r0, r1, r2, r3;
                uint32_t bh0[2], bh1[2], bl0[2], bl1[2];
                ldsm4t(r0, r1, r2, r3, vb + addr);
                bh0[0] = r0; bh0[1] = r1; bh1[0] = r2; bh1[1] = r3;
                ldsm4t(r0, r1, r2, r3, vb + 8192 + addr);
                bl0[0] = r0; bl0[1] = r1; bl1[0] = r2; bl1[1] = r3;
                mma_bf16(o[n4*2], ah[kt], bh0);  mma_bf16(o[n4*2+1], ah[kt], bh1);
                mma_bf16(o[n4*2], ah[kt], bl0);  mma_bf16(o[n4*2+1], ah[kt], bl1);
                mma_bf16(o[n4*2], al[kt], bh0);  mma_bf16(o[n4*2+1], al[kt], bh1);
            }
        }
    }

    #pragma unroll
    for (int g = 0; g < 2; g++) {
        float den = fmaxf(Zm[g], 1e-9f * Zs[g]);
        float rcp = 1.0f / den;
        size_t row = q0 + wid * 16 + (lane >> 2) + g * 8;
        #pragma unroll
        for (int nt = 0; nt < 8; nt++) {
            int col = h * DH + nt * 8 + (lane & 3) * 2;
            uint32_t ph, pl;
            pack2(o[nt][2*g] * rcp, o[nt][2*g+1] * rcp, ph, pl);
            *(uint32_t*)(ctx_h + row * DD + col) = ph;
            *(uint32_t*)(ctx_l + row * DD + col) = pl;
        }
    }
}

// ---------------- pool + normalize ------------------------------------------------
__global__ void pool_kernel(const float* __restrict__ h, const int* __restrict__ mask,
                            float* __restrict__ out)
{
    __shared__ float sent[DD];
    __shared__ float red[32];
    int b = blockIdx.x, tid = threadIdx.x;
    float ms = 0.f;
    for (int s = tid; s < SS; s += 256) ms += (float)mask[b * SS + s];
    ms = blockReduceSum(ms, red);
    float inv = 1.0f / fmaxf(ms, 1e-6f);
    for (int d = tid; d < DD; d += 256) {
        float a = 0.f;
        const float* hp = h + ((size_t)b * SS) * DD + d;
        const int* mp = mask + b * SS;
        for (int s = 0; s < SS; s++) a += hp[(size_t)s * DD] * (float)mp[s];
        sent[d] = a * inv;
    }
    __syncthreads();
    float sq = 0.f;
    for (int d = tid; d < DD; d += 256) sq += sent[d] * sent[d];
    sq = blockReduceSum(sq, red);
    float rn = 1.0f / fmaxf(sqrtf(sq), 1e-12f);
    for (int d = tid; d < DD; d += 256) out[b * DD + d] = sent[d] * rn;
}

// ---------------- launch -----------------------------------------------------------
extern "C" void kernel_launch(void* const* d_in, const int* in_sizes, int n_in,
                              void* d_out, int out_size)
{
    const int*   input_ids = (const int*)  d_in[0];
    const int*   amask     = (const int*)  d_in[1];
    const float* word_emb  = (const float*)d_in[2];
    const float* pos_emb   = (const float*)d_in[3];
    const float* type_emb  = (const float*)d_in[4];
    const float* emb_g     = (const float*)d_in[5];
    const float* emb_b     = (const float*)d_in[6];
    const float* Wq = (const float*)d_in[7];  const float* bq = (const float*)d_in[8];
    const float* Wk = (const float*)d_in[9];  const float* bk = (const float*)d_in[10];
    const float* Wv = (const float*)d_in[11]; const float* bv = (const float*)d_in[12];
    const float* Wo = (const float*)d_in[13]; const float* bo = (const float*)d_in[14];
    const float* ln1g = (const float*)d_in[15]; const float* ln1b = (const float*)d_in[16];
    const float* Wi = (const float*)d_in[17]; const float* bi = (const float*)d_in[18];
    const float* Wf = (const float*)d_in[19]; const float* bf = (const float*)d_in[20];
    const float* ln2g = (const float*)d_in[21]; const float* ln2b = (const float*)d_in[22];
    float* out = (float*)d_out;

    float *p_h, *p_t1, *p_t2, *p_t3, *p_bqkv;
    __nv_bfloat16 *p_hh, *p_hl, *p_qh, *p_ql, *p_ch, *p_cl, *p_fh, *p_fl;
    __nv_bfloat16 *wqkv_h, *wqkv_l, *wo_h, *wo_l, *wi_h, *wi_l, *wf_h, *wf_l;
    cudaGetSymbolAddress((void**)&p_h,  g_h);
    cudaGetSymbolAddress((void**)&p_t1, g_t1);
    cudaGetSymbolAddress((void**)&p_t2, g_t2);
    cudaGetSymbolAddress((void**)&p_t3, g_t3);
    cudaGetSymbolAddress((void**)&p_bqkv, g_bqkv);
    cudaGetSymbolAddress((void**)&p_hh, g_h_hi);
    cudaGetSymbolAddress((void**)&p_hl, g_h_lo);
    cudaGetSymbolAddress((void**)&p_qh, g_qkv_h);
    cudaGetSymbolAddress((void**)&p_ql, g_qkv_l);
    cudaGetSymbolAddress((void**)&p_ch, g_ctx_hi);
    cudaGetSymbolAddress((void**)&p_cl, g_ctx_lo);
    cudaGetSymbolAddress((void**)&p_fh, g_ff_hi);
    cudaGetSymbolAddress((void**)&p_fl, g_ff_lo);
    cudaGetSymbolAddress((void**)&wqkv_h, g_Wqkv_h); cudaGetSymbolAddress((void**)&wqkv_l, g_Wqkv_l);
    cudaGetSymbolAddress((void**)&wo_h, g_WoT_h);    cudaGetSymbolAddress((void**)&wo_l, g_WoT_l);
    cudaGetSymbolAddress((void**)&wi_h, g_WiT_h);    cudaGetSymbolAddress((void**)&wi_l, g_WiT_l);
    cudaGetSymbolAddress((void**)&wf_h, g_WfT_h);    cudaGetSymbolAddress((void**)&wf_l, g_WfT_l);

    cudaFuncSetAttribute(gemm_mma, cudaFuncAttributeMaxDynamicSharedMemorySize, GEMM_SMEM);
    cudaFuncSetAttribute(attn_flash, cudaFuncAttributeMaxDynamicSharedMemorySize, ATTN_SMEM);

    trans_all<<<LL * 6912, dim3(32, 8)>>>(Wq, Wk, Wv, Wo, Wi, Wf);
    fuse_bias<<<(LL * NQKV + 255) / 256, 256>>>(bq, bk, bv);
    embed_ln_kernel<<<MTOK, 384>>>(input_ids, word_emb, pos_emb, type_emb,
                                   emb_g, emb_b, p_h, p_hh, p_hl);

    dim3 gQKV(NQKV / 128, MTOK / 128, 1);
    dim3 gSK3(DD   / 128, MTOK / 128, 3);
    dim3 gFF (FFD  / 128, MTOK / 128, 1);

    for (int l = 0; l < LL; l++) {
        size_t wdd = (size_t)l * DD * DD;
        size_t wdf = (size_t)l * DD * FFD;
        size_t wqk = (size_t)l * NQKV * DD;

        gemm_mma<<<gQKV, 256, GEMM_SMEM>>>(p_hh, p_hl, wqkv_h + wqk, wqkv_l + wqk,
                                           p_bqkv + l * NQKV, nullptr, nullptr, nullptr,
                                           p_qh, p_ql, MTOK, NQKV, DD, DD, 3);

        attn_flash<<<dim3(4, HH, BB), 256, ATTN_SMEM>>>(p_qh, p_ql, amask, p_ch, p_cl);

        gemm_mma<<<gSK3, 256, GEMM_SMEM>>>(p_ch, p_cl, wo_h + wdd, wo_l + wdd,
                                           nullptr, p_t1, p_t2, p_t3, nullptr, nullptr,
                                           MTOK, DD, DD / 3, DD, 0);
        ln_sum3_kernel<<<MTOK, 384>>>(p_t1, p_t2, p_t3, bo + l * DD, p_h,
                                      ln1g + l * DD, ln1b + l * DD, p_h, p_hh, p_hl);

        gemm_mma<<<gFF, 256, GEMM_SMEM>>>(p_hh, p_hl, wi_h + wdf, wi_l + wdf,
                                          bi + l * FFD, nullptr, nullptr, nullptr,
                                          p_fh, p_fl, MTOK, FFD, DD, DD, 1);

        gemm_mma<<<gSK3, 256, GEMM_SMEM>>>(p_fh, p_fl, wf_h + wdf, wf_l + wdf,
                                           nullptr, p_t1, p_t2, p_t3, nullptr, nullptr,
                                           MTOK, DD, FFD / 3, FFD, 0);
        ln_sum3_kernel<<<MTOK, 384>>>(p_t1, p_t2, p_t3, bf + l * DD, p_h,
                                      ln2g + l * DD, ln2b + l * DD, p_h, p_hh, p_hl);
    }

    pool_kernel<<<BB, 256>>>(p_h, amask, out);
}

// round 15
// speedup vs baseline: 2.4774x; 1.3841x over previous
#include <cuda_runtime.h>
#include <cuda_fp16.h>
#include <math.h>
#include <stdint.h>

#define BB 8
#define SS 512
#define DD 768
#define HH 12
#define DH 64
#define LL 12
#define FFD 3072
#define MTOK (BB*SS)
#define NQKV 2304

__device__ __align__(256) float g_h [MTOK*DD];
__device__ __align__(256) float g_t1[MTOK*DD];
__device__ __align__(256) float g_t2[MTOK*DD];
__device__ __align__(256) float g_t3[MTOK*DD];

__device__ __align__(256) __half g_h16  [MTOK*DD];
__device__ __align__(256) __half g_qkv_h[MTOK*NQKV];
__device__ __align__(256) __half g_qkv_l[MTOK*NQKV];
__device__ __align__(256) __half g_ctx16[MTOK*DD];
__device__ __align__(256) __half g_ff16 [MTOK*FFD];

__device__ __align__(256) __half g_Wqkv_h[LL*NQKV*DD];
__device__ __align__(256) __half g_Wqkv_l[LL*NQKV*DD];
__device__ __align__(256) __half g_WoT_h[LL*DD*DD];
__device__ __align__(256) __half g_WoT_l[LL*DD*DD];
__device__ __align__(256) __half g_WiT_h[LL*DD*FFD];
__device__ __align__(256) __half g_WiT_l[LL*DD*FFD];
__device__ __align__(256) __half g_WfT_h[LL*DD*FFD];
__device__ __align__(256) __half g_WfT_l[LL*DD*FFD];
__device__ __align__(256) float g_bqkv[LL*NQKV];

// ---------------- helpers ------------------------------------------------------
__device__ __forceinline__ uint32_t smem_u32(const void* p) {
    uint32_t a;
    asm("{ .reg .u64 t; cvta.to.shared.u64 t, %1; cvt.u32.u64 %0, t; }" : "=r"(a) : "l"(p));
    return a;
}
__device__ __forceinline__ uint32_t swz(uint32_t o) { return o ^ ((o >> 3) & 0x70); }
__device__ __forceinline__ void cpa16(uint32_t saddr, const void* g) {
    asm volatile("cp.async.cg.shared.global [%0], [%1], 16;" :: "r"(saddr), "l"(g));
}
__device__ __forceinline__ void cp_commit() {
    asm volatile("cp.async.commit_group;" ::: "memory");
}
template <int N>
__device__ __forceinline__ void cp_wait() {
    asm volatile("cp.async.wait_group %0;" :: "n"(N) : "memory");
}
__device__ __forceinline__ void ldsm4(uint32_t& r0, uint32_t& r1, uint32_t& r2, uint32_t& r3,
                                      uint32_t addr) {
    asm volatile("ldmatrix.sync.aligned.m8n8.x4.shared.b16 {%0,%1,%2,%3}, [%4];"
                 : "=r"(r0), "=r"(r1), "=r"(r2), "=r"(r3) : "r"(addr));
}
__device__ __forceinline__ void ldsm4t(uint32_t& r0, uint32_t& r1, uint32_t& r2, uint32_t& r3,
                                       uint32_t addr) {
    asm volatile("ldmatrix.sync.aligned.m8n8.x4.trans.shared.b16 {%0,%1,%2,%3}, [%4];"
                 : "=r"(r0), "=r"(r1), "=r"(r2), "=r"(r3) : "r"(addr));
}
__device__ __forceinline__ void mma_f16(float* d, const uint32_t* a, const uint32_t* b) {
    asm volatile("mma.sync.aligned.m16n8k16.row.col.f32.f16.f16.f32 "
                 "{%0,%1,%2,%3}, {%4,%5,%6,%7}, {%8,%9}, {%0,%1,%2,%3};"
                 : "+f"(d[0]), "+f"(d[1]), "+f"(d[2]), "+f"(d[3])
                 : "r"(a[0]), "r"(a[1]), "r"(a[2]), "r"(a[3]), "r"(b[0]), "r"(b[1]));
}
__device__ __forceinline__ void split_h(float x, __half& hi, __half& lo) {
    hi = __float2half(x);
    lo = __float2half(x - __half2float(hi));
}
__device__ __forceinline__ uint32_t packh(float a, float b) {
    __half2 t(__float2half(a), __float2half(b));
    return *(uint32_t*)&t;
}
__device__ __forceinline__ void packh2(float a, float b, uint32_t& ph, uint32_t& pl) {
    __half ha, la, hb, lb;
    split_h(a, ha, la); split_h(b, hb, lb);
    __half2 th(ha, hb), tl(la, lb);
    ph = *(uint32_t*)&th; pl = *(uint32_t*)&tl;
}
__device__ __forceinline__ float blockReduceSum(float v, float* red) {
    int lane = threadIdx.x & 31, w = threadIdx.x >> 5;
    #pragma unroll
    for (int o = 16; o; o >>= 1) v += __shfl_xor_sync(0xffffffffu, v, o);
    if (lane == 0) red[w] = v;
    __syncthreads();
    float t = (threadIdx.x < (blockDim.x >> 5)) ? red[threadIdx.x] : 0.f;
    if (w == 0) {
        #pragma unroll
        for (int o = 16; o; o >>= 1) t += __shfl_xor_sync(0xffffffffu, t, o);
        if (lane == 0) red[0] = t;
    }
    __syncthreads();
    return red[0];
}

// ---------------- weight prep ------------------------------------------------------
__global__ void trans_all(const float* __restrict__ Wq, const float* __restrict__ Wk,
                          const float* __restrict__ Wv, const float* __restrict__ Wo,
                          const float* __restrict__ Wi, const float* __restrict__ Wf)
{
    __shared__ float tsm[32][33];
    int t = blockIdx.x;
    int l = t / 6912, r = t % 6912;
    const float* src; __half *dh, *dl;
    int K, N, rowoff, nx, ky;
    if (r < 1728) {
        int w = r / 576, q2 = r % 576;
        src = (w == 0 ? Wq : w == 1 ? Wk : Wv) + (size_t)l * DD * DD;
        dh = g_Wqkv_h + (size_t)l * NQKV * DD; dl = g_Wqkv_l + (size_t)l * NQKV * DD;
        K = DD; N = DD; rowoff = w * DD; ky = q2 / 24; nx = q2 % 24;
    } else if (r < 2304) {
        int q2 = r - 1728;
        src = Wo + (size_t)l * DD * DD;
        dh = g_WoT_h + (size_t)l * DD * DD; dl = g_WoT_l + (size_t)l * DD * DD;
        K = DD; N = DD; rowoff = 0; ky = q2 / 24; nx = q2 % 24;
    } else if (r < 4608) {
        int q2 = r - 2304;
        src = Wi + (size_t)l * DD * FFD;
        dh = g_WiT_h + (size_t)l * DD * FFD; dl = g_WiT_l + (size_t)l * DD * FFD;
        K = DD; N = FFD; rowoff = 0; ky = q2 / 96; nx = q2 % 96;
    } else {
        int q2 = r - 4608;
        src = Wf + (size_t)l * FFD * DD;
        dh = g_WfT_h + (size_t)l * DD * FFD; dl = g_WfT_l + (size_t)l * DD * FFD;
        K = FFD; N = DD; rowoff = 0; ky = q2 / 24; nx = q2 % 24;
    }
    int n0 = nx * 32, k0 = ky * 32;
    int tx = threadIdx.x;
    for (int i = threadIdx.y; i < 32; i += 8)
        tsm[i][tx] = src[(size_t)(k0 + i) * N + n0 + tx];
    __syncthreads();
    for (int i = threadIdx.y; i < 32; i += 8) {
        float v = tsm[tx][i];
        __half hi, lo; split_h(v, hi, lo);
        size_t o = (size_t)(rowoff + n0 + i) * K + k0 + tx;
        dh[o] = hi; dl[o] = lo;
    }
}

__global__ void fuse_bias(const float* __restrict__ bq, const float* __restrict__ bk,
                          const float* __restrict__ bv)
{
    int i = blockIdx.x * 256 + threadIdx.x;
    if (i >= LL * NQKV) return;
    int l = i / NQKV, n = i % NQKV;
    g_bqkv[i] = (n < DD) ? bq[l * DD + n]
              : (n < 2 * DD) ? bk[l * DD + n - DD]
                             : bv[l * DD + n - 2 * DD];
}

// ---------------- embedding LN (384 thr, vectorized, fp16-single out) --------------
__global__ __launch_bounds__(384)
void embed_ln_kernel(const int* __restrict__ ids, const float* __restrict__ we,
                     const float* __restrict__ pe, const float* __restrict__ te,
                     const float* __restrict__ gam, const float* __restrict__ bet,
                     float* __restrict__ out, __half* __restrict__ oh)
{
    __shared__ float red[32];
    int tok = blockIdx.x, s = tok & (SS - 1), id = ids[tok], tid = threadIdx.x;
    int d = tid * 2;
    float2 w2 = *(const float2*)(we + (size_t)id * DD + d);
    float2 p2 = *(const float2*)(pe + (size_t)s * DD + d);
    float2 t2 = *(const float2*)(te + d);
    float x0 = w2.x + p2.x + t2.x;
    float x1 = w2.y + p2.y + t2.y;
    float mu = blockReduceSum(x0 + x1, red) * (1.0f / DD);
    float d0 = x0 - mu, d1 = x1 - mu;
    float var = blockReduceSum(d0 * d0 + d1 * d1, red) * (1.0f / DD);
    float r = rsqrtf(var + 1e-12f);
    float2 g2 = *(const float2*)(gam + d);
    float2 b2 = *(const float2*)(bet + d);
    float o0 = d0 * r * g2.x + b2.x;
    float o1 = d1 * r * g2.y + b2.y;
    size_t ro = (size_t)tok * DD + d;
    *(float2*)(out + ro) = make_float2(o0, o1);
    *(uint32_t*)(oh + ro) = packh(o0, o1);
}

// ---------------- LN over (p0+p1+p2+bias+res), fp16-single out ---------------------
__global__ __launch_bounds__(384)
void ln_sum3_kernel(const float* __restrict__ p0, const float* __restrict__ p1,
                    const float* __restrict__ p2,
                    const float* __restrict__ bias, const float* __restrict__ res,
                    const float* __restrict__ gam, const float* __restrict__ bet,
                    float* __restrict__ out, __half* __restrict__ oh)
{
    __shared__ float red[32];
    int row = blockIdx.x, tid = threadIdx.x;
    int d = tid * 2;
    size_t ro = (size_t)row * DD + d;
    float2 a2 = *(const float2*)(p0 + ro);
    float2 c2 = *(const float2*)(p1 + ro);
    float2 e2 = *(const float2*)(p2 + ro);
    float2 r2 = *(const float2*)(res + ro);
    float2 bb = *(const float2*)(bias + d);
    float x0 = a2.x + c2.x + e2.x + r2.x + bb.x;
    float x1 = a2.y + c2.y + e2.y + r2.y + bb.y;
    float mu = blockReduceSum(x0 + x1, red) * (1.0f / DD);
    float d0 = x0 - mu, d1 = x1 - mu;
    float var = blockReduceSum(d0 * d0 + d1 * d1, red) * (1.0f / DD);
    float r = rsqrtf(var + 1e-12f);
    float2 g2 = *(const float2*)(gam + d);
    float2 be2 = *(const float2*)(bet + d);
    float o0 = d0 * r * g2.x + be2.x;
    float o1 = d1 * r * g2.y + be2.y;
    *(float2*)(out + ro) = make_float2(o0, o1);
    *(uint32_t*)(oh + ro) = packh(o0, o1);
}

// ---------------- GEMM: A single fp16, B hi/lo fp16, 2 products ---------------------
// mode 0: fp32 partial -> Cz ; mode 1: +bias,GELU -> Ch fp16 ; mode 3: QKV
#define GSTG 3
#define GEMM_SMEM (GSTG*24576 + 1024)

__global__ __launch_bounds__(256, 2)
void gemm_mma(const __half* __restrict__ A,
              const __half* __restrict__ Bh, const __half* __restrict__ Bl,
              const float* __restrict__ bias,
              float* __restrict__ C, float* __restrict__ C2, float* __restrict__ C3,
              __half* __restrict__ Ch, __half* __restrict__ Cl,
              int N, int K, int lda, int mode)
{
    extern __shared__ char dsm[];
    uint32_t raw = smem_u32(dsm);
    uint32_t s0 = (raw + 1023) & ~1023u;

    int tid = threadIdx.x, wid = tid >> 5, lane = tid & 31;
    int wm = wid & 1, wn = wid >> 1;
    long mBase = (long)blockIdx.y * 128;
    long nBase = (long)blockIdx.x * 128;
    int kOff = blockIdx.z * K;

    float acc[4][4][4];
    #pragma unroll
    for (int i = 0; i < 4; i++)
        #pragma unroll
        for (int j = 0; j < 4; j++)
            #pragma unroll
            for (int q = 0; q < 4; q++) acc[i][j][q] = 0.f;

    int lrow = tid >> 1, lkc0 = (tid & 1) * 2;
    const __half* Ap  = A  + (size_t)(mBase + lrow) * lda + kOff;
    const __half* Bhp = Bh + (size_t)(nBase + lrow) * lda + kOff;
    const __half* Blp = Bl + (size_t)(nBase + lrow) * lda + kOff;
    uint32_t sw0 = swz(lrow * 64 + lkc0 * 16);
    uint32_t sw1 = swz(lrow * 64 + (lkc0 + 1) * 16);
    const int nIt = K / 32;

    #pragma unroll 1
    for (int pf = 0; pf < 2; pf++) {
        uint32_t sb = s0 + pf * 24576;
        int k0 = pf * 32 + lkc0 * 8;
        cpa16(sb + sw0, Ap + k0);           cpa16(sb + sw1, Ap + k0 + 8);
        cpa16(sb + 8192 + sw0, Bhp + k0);   cpa16(sb + 8192 + sw1, Bhp + k0 + 8);
        cpa16(sb + 16384 + sw0, Blp + k0);  cpa16(sb + 16384 + sw1, Blp + k0 + 8);
        cp_commit();
    }

    #pragma unroll 1
    for (int it = 0; it < nIt; ++it) {
        if (it < nIt - 1) cp_wait<1>(); else cp_wait<0>();
        __syncthreads();
        if (it + 2 < nIt) {
            uint32_t sb = s0 + ((it + 2) % GSTG) * 24576;
            int k0 = (it + 2) * 32 + lkc0 * 8;
            cpa16(sb + sw0, Ap + k0);           cpa16(sb + sw1, Ap + k0 + 8);
            cpa16(sb + 8192 + sw0, Bhp + k0);   cpa16(sb + 8192 + sw1, Bhp + k0 + 8);
            cpa16(sb + 16384 + sw0, Blp + k0);  cpa16(sb + 16384 + sw1, Blp + k0 + 8);
            cp_commit();
        }
        uint32_t base = s0 + (it % GSTG) * 24576;
        #pragma unroll
        for (int ks = 0; ks < 2; ks++) {
            uint32_t kcol = (ks * 2 + (lane >> 4)) * 16;
            int brow = wn * 32 + (lane & 15);
            uint32_t bh[4][2], bl[4][2];
            #pragma unroll
            for (int n2 = 0; n2 < 2; n2++) {
                uint32_t r0, r1, r2, r3;
                ldsm4(r0, r1, r2, r3, base + 8192 + swz((brow + n2 * 16) * 64 + kcol));
                bh[n2*2][0] = r0; bh[n2*2][1] = r2; bh[n2*2+1][0] = r1; bh[n2*2+1][1] = r3;
                ldsm4(r0, r1, r2, r3, base + 16384 + swz((brow + n2 * 16) * 64 + kcol));
                bl[n2*2][0] = r0; bl[n2*2][1] = r2; bl[n2*2+1][0] = r1; bl[n2*2+1][1] = r3;
            }
            int arow = wm * 64 + (lane & 15);
            #pragma unroll
            for (int mt = 0; mt < 4; mt++) {
                uint32_t a[4];
                ldsm4(a[0], a[1], a[2], a[3], base + swz((arow + mt * 16) * 64 + kcol));
                #pragma unroll
                for (int nt = 0; nt < 4; nt++) mma_f16(acc[mt][nt], a, bh[nt]);
                #pragma unroll
                for (int nt = 0; nt < 4; nt++) mma_f16(acc[mt][nt], a, bl[nt]);
            }
        }
    }

    float* dst = (blockIdx.z == 0) ? C : (blockIdx.z == 1 ? C2 : C3);
    #pragma unroll
    for (int mt = 0; mt < 4; mt++) {
        #pragma unroll
        for (int half2_ = 0; half2_ < 2; half2_++) {
            long m = mBase + wm * 64 + mt * 16 + (lane >> 2) + half2_ * 8;
            #pragma unroll
            for (int nt = 0; nt < 4; nt++) {
                long n0 = nBase + wn * 32 + nt * 8 + (lane & 3) * 2;
                float v0 = acc[mt][nt][half2_ * 2];
                float v1 = acc[mt][nt][half2_ * 2 + 1];
                if (mode == 0) {
                    *(float2*)(dst + m * N + n0) = make_float2(v0, v1);
                } else if (mode == 1) {
                    v0 += __ldg(bias + n0); v1 += __ldg(bias + n0 + 1);
                    v0 = 0.5f * v0 * (1.0f + erff(v0 * 0.70710678118654752f));
                    v1 = 0.5f * v1 * (1.0f + erff(v1 * 0.70710678118654752f));
                    *(uint32_t*)(Ch + m * N + n0) = packh(v0, v1);
                } else {
                    v0 += __ldg(bias + n0); v1 += __ldg(bias + n0 + 1);
                    if (n0 < DD) {
                        *(uint32_t*)(Ch + m * N + n0) = packh(v0 * 0.125f, v1 * 0.125f);
                    } else {
                        uint32_t ph, pl; packh2(v0, v1, ph, pl);
                        *(uint32_t*)(Ch + m * N + n0) = ph;
                        *(uint32_t*)(Cl + m * N + n0) = pl;
                    }
                }
            }
        }
    }
}

// ---------------- flash attention: Q,P single fp16; K,V hi/lo ----------------------
#define A_QH 0
#define A_KV 16384
#define A_MK (16384 + 98304)
#define ATTN_SMEM (114688 + 2048 + 1024)

__global__ __launch_bounds__(256, 1)
void attn_flash(const __half* __restrict__ qkv_h, const __half* __restrict__ qkv_l,
                const int* __restrict__ mask, __half* __restrict__ ctx16)
{
    extern __shared__ char dsm[];
    uint32_t raw = smem_u32(dsm);
    uint32_t s0 = (raw + 1023) & ~1023u;
    char* sm = dsm + (s0 - raw);

    int b = blockIdx.z, h = blockIdx.y, qt = blockIdx.x;
    int tid = threadIdx.x, wid = tid >> 5, lane = tid & 31;
    int q0 = b * SS + qt * 128;
    int k0g = b * SS;

    float* maskf = (float*)(sm + A_MK);
    for (int i = tid; i < SS; i += 256) maskf[i] = (float)mask[b * SS + i];

    #pragma unroll
    for (int r2 = 0; r2 < 4; r2++) {
        int i = tid + r2 * 256;
        int row = i >> 3, c = i & 7;
        uint32_t sw = swz(row * 128 + c * 16);
        cpa16(s0 + A_QH + sw, qkv_h + (size_t)(q0 + row) * NQKV + h * DH + c * 8);
    }
    cp_commit();

    auto ldKV = [&](int ch, int stg) {
        uint32_t kb = s0 + A_KV + stg * 32768;
        #pragma unroll
        for (int r2 = 0; r2 < 2; r2++) {
            int i = tid + r2 * 256;
            int row = i >> 3, c = i & 7;
            uint32_t sw = swz(row * 128 + c * 16);
            size_t gk = (size_t)(k0g + ch * 64 + row) * NQKV + DD + h * DH + c * 8;
            cpa16(kb + sw,         qkv_h + gk);
            cpa16(kb + 8192 + sw,  qkv_l + gk);
            cpa16(kb + 16384 + sw, qkv_h + gk + DD);
            cpa16(kb + 24576 + sw, qkv_l + gk + DD);
        }
        cp_commit();
    };
    ldKV(0, 0);
    ldKV(1, 1);

    cp_wait<2>(); __syncthreads();

    uint32_t qh[4][4];
    {
        int qr = wid * 16 + (lane & 15);
        #pragma unroll
        for (int ks = 0; ks < 4; ks++) {
            uint32_t o2 = swz(qr * 128 + (ks * 2 + (lane >> 4)) * 16);
            ldsm4(qh[ks][0], qh[ks][1], qh[ks][2], qh[ks][3], s0 + A_QH + o2);
        }
    }

    float M[2] = {-1e30f, -1e30f}, Zs[2] = {0.f, 0.f}, Zm[2] = {0.f, 0.f};
    float o[8][4];
    #pragma unroll
    for (int i = 0; i < 8; i++)
        #pragma unroll
        for (int j = 0; j < 4; j++) o[i][j] = 0.f;

    #pragma unroll 1
    for (int ch = 0; ch < 8; ch++) {
        if (ch < 7) cp_wait<1>(); else cp_wait<0>();
        __syncthreads();
        if (ch + 2 < 8) ldKV(ch + 2, (ch + 2) % 3);

        uint32_t kb = s0 + A_KV + (ch % 3) * 32768;
        float s[8][4];
        #pragma unroll
        for (int i = 0; i < 8; i++)
            #pragma unroll
            for (int j = 0; j < 4; j++) s[i][j] = 0.f;

        #pragma unroll
        for (int n4 = 0; n4 < 4; n4++) {
            int br = n4 * 16 + (lane & 15);
            #pragma unroll
            for (int ks = 0; ks < 4; ks++) {
                uint32_t kcol = (ks * 2 + (lane >> 4)) * 16;
                uint32_t r0, r1, r2, r3;
                uint32_t bh0[2], bh1[2], bl0[2], bl1[2];
                ldsm4(r0, r1, r2, r3, kb + swz(br * 128 + kcol));
                bh0[0] = r0; bh0[1] = r2; bh1[0] = r1; bh1[1] = r3;
                ldsm4(r0, r1, r2, r3, kb + 8192 + swz(br * 128 + kcol));
                bl0[0] = r0; bl0[1] = r2; bl1[0] = r1; bl1[1] = r3;
                mma_f16(s[n4*2], qh[ks], bh0);  mma_f16(s[n4*2+1], qh[ks], bh1);
                mma_f16(s[n4*2], qh[ks], bl0);  mma_f16(s[n4*2+1], qh[ks], bl1);
            }
        }

        #pragma unroll
        for (int g = 0; g < 2; g++) {
            float mx = -1e30f;
            #pragma unroll
            for (int nt = 0; nt < 8; nt++)
                mx = fmaxf(mx, fmaxf(s[nt][2*g], s[nt][2*g+1]));
            mx = fmaxf(mx, __shfl_xor_sync(0xffffffffu, mx, 1));
            mx = fmaxf(mx, __shfl_xor_sync(0xffffffffu, mx, 2));
            float Mn = fmaxf(M[g], mx);
            float fac = __expf(M[g] - Mn);
            float zc = 0.f, zmc = 0.f;
            #pragma unroll
            for (int nt = 0; nt < 8; nt++) {
                #pragma unroll
                for (int e = 0; e < 2; e++) {
                    int col = ch * 64 + nt * 8 + (lane & 3) * 2 + e;
                    float ex = __expf(s[nt][2*g+e] - Mn);
                    float mm = maskf[col];
                    zc += ex; zmc += ex * mm;
                    s[nt][2*g+e] = ex * mm;
                }
            }
            zc += __shfl_xor_sync(0xffffffffu, zc, 1);
            zc += __shfl_xor_sync(0xffffffffu, zc, 2);
            zmc += __shfl_xor_sync(0xffffffffu, zmc, 1);
            zmc += __shfl_xor_sync(0xffffffffu, zmc, 2);
            Zs[g] = Zs[g] * fac + zc;
            Zm[g] = Zm[g] * fac + zmc;
            M[g] = Mn;
            #pragma unroll
            for (int nt = 0; nt < 8; nt++) { o[nt][2*g] *= fac; o[nt][2*g+1] *= fac; }
        }

        uint32_t ah[4][4];
        #pragma unroll
        for (int kt = 0; kt < 4; kt++) {
            ah[kt][0] = packh(s[2*kt][0],   s[2*kt][1]);
            ah[kt][1] = packh(s[2*kt][2],   s[2*kt][3]);
            ah[kt][2] = packh(s[2*kt+1][0], s[2*kt+1][1]);
            ah[kt][3] = packh(s[2*kt+1][2], s[2*kt+1][3]);
        }

        uint32_t vb = kb + 16384;
        #pragma unroll
        for (int n4 = 0; n4 < 4; n4++) {
            #pragma unroll
            for (int kt = 0; kt < 4; kt++) {
                uint32_t addr = swz((kt * 16 + (lane & 15)) * 128 + n4 * 32 + (lane >> 4) * 16);
                uint32_t r0, r1, r2, r3;
                uint32_t bh0[2], bh1[2], bl0[2], bl1[2];
                ldsm4t(r0, r1, r2, r3, vb + addr);
                bh0[0] = r0; bh0[1] = r1; bh1[0] = r2; bh1[1] = r3;
                ldsm4t(r0, r1, r2, r3, vb + 8192 + addr);
                bl0[0] = r0; bl0[1] = r1; bl1[0] = r2; bl1[1] = r3;
                mma_f16(o[n4*2], ah[kt], bh0);  mma_f16(o[n4*2+1], ah[kt], bh1);
                mma_f16(o[n4*2], ah[kt], bl0);  mma_f16(o[n4*2+1], ah[kt], bl1);
            }
        }
    }

    #pragma unroll
    for (int g = 0; g < 2; g++) {
        float den = fmaxf(Zm[g], 1e-9f * Zs[g]);
        float rcp = 1.0f / den;
        size_t row = q0 + wid * 16 + (lane >> 2) + g * 8;
        #pragma unroll
        for (int nt = 0; nt < 8; nt++) {
            int col = h * DH + nt * 8 + (lane & 3) * 2;
            *(uint32_t*)(ctx16 + row * DD + col) = packh(o[nt][2*g] * rcp, o[nt][2*g+1] * rcp);
        }
    }
}

// ---------------- pool + normalize ------------------------------------------------
__global__ void pool_kernel(const float* __restrict__ h, const int* __restrict__ mask,
                            float* __restrict__ out)
{
    __shared__ float sent[DD];
    __shared__ float red[32];
    int b = blockIdx.x, tid = threadIdx.x;
    float ms = 0.f;
    for (int s = tid; s < SS; s += 256) ms += (float)mask[b * SS + s];
    ms = blockReduceSum(ms, red);
    float inv = 1.0f / fmaxf(ms, 1e-6f);
    for (int d = tid; d < DD; d += 256) {
        float a = 0.f;
        const float* hp = h + ((size_t)b * SS) * DD + d;
        const int* mp = mask + b * SS;
        for (int s = 0; s < SS; s++) a += hp[(size_t)s * DD] * (float)mp[s];
        sent[d] = a * inv;
    }
    __syncthreads();
    float sq = 0.f;
    for (int d = tid; d < DD; d += 256) sq += sent[d] * sent[d];
    sq = blockReduceSum(sq, red);
    float rn = 1.0f / fmaxf(sqrtf(sq), 1e-12f);
    for (int d = tid; d < DD; d += 256) out[b * DD + d] = sent[d] * rn;
}

// ---------------- launch -----------------------------------------------------------
extern "C" void kernel_launch(void* const* d_in, const int* in_sizes, int n_in,
                              void* d_out, int out_size)
{
    const int*   input_ids = (const int*)  d_in[0];
    const int*   amask     = (const int*)  d_in[1];
    const float* word_emb  = (const float*)d_in[2];
    const float* pos_emb   = (const float*)d_in[3];
    const float* type_emb  = (const float*)d_in[4];
    const float* emb_g     = (const float*)d_in[5];
    const float* emb_b     = (const float*)d_in[6];
    const float* Wq = (const float*)d_in[7];  const float* bq = (const float*)d_in[8];
    const float* Wk = (const float*)d_in[9];  const float* bk = (const float*)d_in[10];
    const float* Wv = (const float*)d_in[11]; const float* bv = (const float*)d_in[12];
    const float* Wo = (const float*)d_in[13]; const float* bo = (const float*)d_in[14];
    const float* ln1g = (const float*)d_in[15]; const float* ln1b = (const float*)d_in[16];
    const float* Wi = (const float*)d_in[17]; const float* bi = (const float*)d_in[18];
    const float* Wf = (const float*)d_in[19]; const float* bf = (const float*)d_in[20];
    const float* ln2g = (const float*)d_in[21]; const float* ln2b = (const float*)d_in[22];
    float* out = (float*)d_out;

    float *p_h, *p_t1, *p_t2, *p_t3, *p_bqkv;
    __half *p_h16, *p_qh, *p_ql, *p_c16, *p_f16;
    __half *wqkv_h, *wqkv_l, *wo_h, *wo_l, *wi_h, *wi_l, *wf_h, *wf_l;
    cudaGetSymbolAddress((void**)&p_h,  g_h);
    cudaGetSymbolAddress((void**)&p_t1, g_t1);
    cudaGetSymbolAddress((void**)&p_t2, g_t2);
    cudaGetSymbolAddress((void**)&p_t3, g_t3);
    cudaGetSymbolAddress((void**)&p_bqkv, g_bqkv);
    cudaGetSymbolAddress((void**)&p_h16, g_h16);
    cudaGetSymbolAddress((void**)&p_qh, g_qkv_h);
    cudaGetSymbolAddress((void**)&p_ql, g_qkv_l);
    cudaGetSymbolAddress((void**)&p_c16, g_ctx16);
    cudaGetSymbolAddress((void**)&p_f16, g_ff16);
    cudaGetSymbolAddress((void**)&wqkv_h, g_Wqkv_h); cudaGetSymbolAddress((void**)&wqkv_l, g_Wqkv_l);
    cudaGetSymbolAddress((void**)&wo_h, g_WoT_h);    cudaGetSymbolAddress((void**)&wo_l, g_WoT_l);
    cudaGetSymbolAddress((void**)&wi_h, g_WiT_h);    cudaGetSymbolAddress((void**)&wi_l, g_WiT_l);
    cudaGetSymbolAddress((void**)&wf_h, g_WfT_h);    cudaGetSymbolAddress((void**)&wf_l, g_WfT_l);

    cudaFuncSetAttribute(gemm_mma, cudaFuncAttributeMaxDynamicSharedMemorySize, GEMM_SMEM);
    cudaFuncSetAttribute(attn_flash, cudaFuncAttributeMaxDynamicSharedMemorySize, ATTN_SMEM);

    trans_all<<<LL * 6912, dim3(32, 8)>>>(Wq, Wk, Wv, Wo, Wi, Wf);
    fuse_bias<<<(LL * NQKV + 255) / 256, 256>>>(bq, bk, bv);
    embed_ln_kernel<<<MTOK, 384>>>(input_ids, word_emb, pos_emb, type_emb,
                                   emb_g, emb_b, p_h, p_h16);

    dim3 gQKV(NQKV / 128, MTOK / 128, 1);
    dim3 gSK3(DD   / 128, MTOK / 128, 3);
    dim3 gFF (FFD  / 128, MTOK / 128, 1);

    for (int l = 0; l < LL; l++) {
        size_t wdd = (size_t)l * DD * DD;
        size_t wdf = (size_t)l * DD * FFD;
        size_t wqk = (size_t)l * NQKV * DD;

        gemm_mma<<<gQKV, 256, GEMM_SMEM>>>(p_h16, wqkv_h + wqk, wqkv_l + wqk,
                                           p_bqkv + l * NQKV, nullptr, nullptr, nullptr,
                                           p_qh, p_ql, NQKV, DD, DD, 3);

        attn_flash<<<dim3(4, HH, BB), 256, ATTN_SMEM>>>(p_qh, p_ql, amask, p_c16);

        gemm_mma<<<gSK3, 256, GEMM_SMEM>>>(p_c16, wo_h + wdd, wo_l + wdd,
                                           nullptr, p_t1, p_t2, p_t3, nullptr, nullptr,
                                           DD, DD / 3, DD, 0);
        ln_sum3_kernel<<<MTOK, 384>>>(p_t1, p_t2, p_t3, bo + l * DD, p_h,
                                      ln1g + l * DD, ln1b + l * DD, p_h, p_h16);

        gemm_mma<<<gFF, 256, GEMM_SMEM>>>(p_h16, wi_h + wdf, wi_l + wdf,
                                          bi + l * FFD, nullptr, nullptr, nullptr,
                                          p_f16, nullptr, FFD, DD, DD, 1);

        gemm_mma<<<gSK3, 256, GEMM_SMEM>>>(p_f16, wf_h + wdf, wf_l + wdf,
                                           nullptr, p_t1, p_t2, p_t3, nullptr, nullptr,
                                           DD, FFD / 3, FFD, 0);
        ln_sum3_kernel<<<MTOK, 384>>>(p_t1, p_t2, p_t3, bf + l * DD, p_h,
                                      ln2g + l * DD, ln2b + l * DD, p_h, p_h16);
    }

    pool_kernel<<<BB, 256>>>(p_h, amask, out);
}

// round 17
// speedup vs baseline: 3.9305x; 1.5865x over previous
#include <cuda_runtime.h>
#include <cuda_fp16.h>
#include <math.h>
#include <stdint.h>

#define BB 8
#define SS 512
#define DD 768
#define HH 12
#define DH 64
#define LL 12
#define FFD 3072
#define MTOK (BB*SS)
#define NQKV 2304

__device__ __align__(256) float g_h [MTOK*DD];
__device__ __align__(256) float g_t1[MTOK*DD];
__device__ __align__(256) float g_t2[MTOK*DD];
__device__ __align__(256) float g_t3[MTOK*DD];

__device__ __align__(256) __half g_h16  [MTOK*DD];
__device__ __align__(256) __half g_qkv16[MTOK*NQKV];
__device__ __align__(256) __half g_ctx16[MTOK*DD];
__device__ __align__(256) __half g_ff16 [MTOK*FFD];

__device__ __align__(256) __half g_Wqkv[LL*NQKV*DD];
__device__ __align__(256) __half g_WoT [LL*DD*DD];
__device__ __align__(256) __half g_WiT [LL*DD*FFD];
__device__ __align__(256) __half g_WfT [LL*DD*FFD];
__device__ __align__(256) float g_bqkv[LL*NQKV];

// ---------------- helpers ------------------------------------------------------
__device__ __forceinline__ uint32_t smem_u32(const void* p) {
    uint32_t a;
    asm("{ .reg .u64 t; cvta.to.shared.u64 t, %1; cvt.u32.u64 %0, t; }" : "=r"(a) : "l"(p));
    return a;
}
__device__ __forceinline__ uint32_t swz(uint32_t o) { return o ^ ((o >> 3) & 0x70); }
__device__ __forceinline__ void cpa16(uint32_t saddr, const void* g) {
    asm volatile("cp.async.cg.shared.global [%0], [%1], 16;" :: "r"(saddr), "l"(g));
}
__device__ __forceinline__ void cp_commit() {
    asm volatile("cp.async.commit_group;" ::: "memory");
}
template <int N>
__device__ __forceinline__ void cp_wait() {
    asm volatile("cp.async.wait_group %0;" :: "n"(N) : "memory");
}
__device__ __forceinline__ void ldsm4(uint32_t& r0, uint32_t& r1, uint32_t& r2, uint32_t& r3,
                                      uint32_t addr) {
    asm volatile("ldmatrix.sync.aligned.m8n8.x4.shared.b16 {%0,%1,%2,%3}, [%4];"
                 : "=r"(r0), "=r"(r1), "=r"(r2), "=r"(r3) : "r"(addr));
}
__device__ __forceinline__ void ldsm4t(uint32_t& r0, uint32_t& r1, uint32_t& r2, uint32_t& r3,
                                       uint32_t addr) {
    asm volatile("ldmatrix.sync.aligned.m8n8.x4.trans.shared.b16 {%0,%1,%2,%3}, [%4];"
                 : "=r"(r0), "=r"(r1), "=r"(r2), "=r"(r3) : "r"(addr));
}
__device__ __forceinline__ void mma_f16(float* d, const uint32_t* a, const uint32_t* b) {
    asm volatile("mma.sync.aligned.m16n8k16.row.col.f32.f16.f16.f32 "
                 "{%0,%1,%2,%3}, {%4,%5,%6,%7}, {%8,%9}, {%0,%1,%2,%3};"
                 : "+f"(d[0]), "+f"(d[1]), "+f"(d[2]), "+f"(d[3])
                 : "r"(a[0]), "r"(a[1]), "r"(a[2]), "r"(a[3]), "r"(b[0]), "r"(b[1]));
}
__device__ __forceinline__ uint32_t packh(float a, float b) {
    __half2 t(__float2half(a), __float2half(b));
    return *(uint32_t*)&t;
}
__device__ __forceinline__ float blockReduceSum(float v, float* red) {
    int lane = threadIdx.x & 31, w = threadIdx.x >> 5;
    #pragma unroll
    for (int o = 16; o; o >>= 1) v += __shfl_xor_sync(0xffffffffu, v, o);
    if (lane == 0) red[w] = v;
    __syncthreads();
    float t = (threadIdx.x < (blockDim.x >> 5)) ? red[threadIdx.x] : 0.f;
    if (w == 0) {
        #pragma unroll
        for (int o = 16; o; o >>= 1) t += __shfl_xor_sync(0xffffffffu, t, o);
        if (lane == 0) red[0] = t;
    }
    __syncthreads();
    return red[0];
}

// ---------------- weight prep ------------------------------------------------------
__global__ void trans_all(const float* __restrict__ Wq, const float* __restrict__ Wk,
                          const float* __restrict__ Wv, const float* __restrict__ Wo,
                          const float* __restrict__ Wi, const float* __restrict__ Wf)
{
    __shared__ float tsm[32][33];
    int t = blockIdx.x;
    int l = t / 6912, r = t % 6912;
    const float* src; __half* dh;
    int K, N, rowoff, nx, ky;
    if (r < 1728) {
        int w = r / 576, q2 = r % 576;
        src = (w == 0 ? Wq : w == 1 ? Wk : Wv) + (size_t)l * DD * DD;
        dh = g_Wqkv + (size_t)l * NQKV * DD;
        K = DD; N = DD; rowoff = w * DD; ky = q2 / 24; nx = q2 % 24;
    } else if (r < 2304) {
        int q2 = r - 1728;
        src = Wo + (size_t)l * DD * DD;
        dh = g_WoT + (size_t)l * DD * DD;
        K = DD; N = DD; rowoff = 0; ky = q2 / 24; nx = q2 % 24;
    } else if (r < 4608) {
        int q2 = r - 2304;
        src = Wi + (size_t)l * DD * FFD;
        dh = g_WiT + (size_t)l * DD * FFD;
        K = DD; N = FFD; rowoff = 0; ky = q2 / 96; nx = q2 % 96;
    } else {
        int q2 = r - 4608;
        src = Wf + (size_t)l * FFD * DD;
        dh = g_WfT + (size_t)l * DD * FFD;
        K = FFD; N = DD; rowoff = 0; ky = q2 / 24; nx = q2 % 24;
    }
    int n0 = nx * 32, k0 = ky * 32;
    int tx = threadIdx.x;
    for (int i = threadIdx.y; i < 32; i += 8)
        tsm[i][tx] = src[(size_t)(k0 + i) * N + n0 + tx];
    __syncthreads();
    for (int i = threadIdx.y; i < 32; i += 8)
        dh[(size_t)(rowoff + n0 + i) * K + k0 + tx] = __float2half(tsm[tx][i]);
}

__global__ void fuse_bias(const float* __restrict__ bq, const float* __restrict__ bk,
                          const float* __restrict__ bv)
{
    int i = blockIdx.x * 256 + threadIdx.x;
    if (i >= LL * NQKV) return;
    int l = i / NQKV, n = i % NQKV;
    g_bqkv[i] = (n < DD) ? bq[l * DD + n]
              : (n < 2 * DD) ? bk[l * DD + n - DD]
                             : bv[l * DD + n - 2 * DD];
}

// ---------------- embedding LN ------------------------------------------------------
__global__ __launch_bounds__(384)
void embed_ln_kernel(const int* __restrict__ ids, const float* __restrict__ we,
                     const float* __restrict__ pe, const float* __restrict__ te,
                     const float* __restrict__ gam, const float* __restrict__ bet,
                     float* __restrict__ out, __half* __restrict__ oh)
{
    __shared__ float red[32];
    int tok = blockIdx.x, s = tok & (SS - 1), id = ids[tok], tid = threadIdx.x;
    int d = tid * 2;
    float2 w2 = *(const float2*)(we + (size_t)id * DD + d);
    float2 p2 = *(const float2*)(pe + (size_t)s * DD + d);
    float2 t2 = *(const float2*)(te + d);
    float x0 = w2.x + p2.x + t2.x;
    float x1 = w2.y + p2.y + t2.y;
    float mu = blockReduceSum(x0 + x1, red) * (1.0f / DD);
    float d0 = x0 - mu, d1 = x1 - mu;
    float var = blockReduceSum(d0 * d0 + d1 * d1, red) * (1.0f / DD);
    float r = rsqrtf(var + 1e-12f);
    float2 g2 = *(const float2*)(gam + d);
    float2 b2 = *(const float2*)(bet + d);
    float o0 = d0 * r * g2.x + b2.x;
    float o1 = d1 * r * g2.y + b2.y;
    size_t ro = (size_t)tok * DD + d;
    *(float2*)(out + ro) = make_float2(o0, o1);
    *(uint32_t*)(oh + ro) = packh(o0, o1);
}

// ---------------- LN over (p0+p1+p2+bias+res) ---------------------------------------
__global__ __launch_bounds__(384)
void ln_sum3_kernel(const float* __restrict__ p0, const float* __restrict__ p1,
                    const float* __restrict__ p2,
                    const float* __restrict__ bias, const float* __restrict__ res,
                    const float* __restrict__ gam, const float* __restrict__ bet,
                    float* __restrict__ out, __half* __restrict__ oh)
{
    __shared__ float red[32];
    int row = blockIdx.x, tid = threadIdx.x;
    int d = tid * 2;
    size_t ro = (size_t)row * DD + d;
    float2 a2 = *(const float2*)(p0 + ro);
    float2 c2 = *(const float2*)(p1 + ro);
    float2 e2 = *(const float2*)(p2 + ro);
    float2 r2 = *(const float2*)(res + ro);
    float2 bb = *(const float2*)(bias + d);
    float x0 = a2.x + c2.x + e2.x + r2.x + bb.x;
    float x1 = a2.y + c2.y + e2.y + r2.y + bb.y;
    float mu = blockReduceSum(x0 + x1, red) * (1.0f / DD);
    float d0 = x0 - mu, d1 = x1 - mu;
    float var = blockReduceSum(d0 * d0 + d1 * d1, red) * (1.0f / DD);
    float r = rsqrtf(var + 1e-12f);
    float2 g2 = *(const float2*)(gam + d);
    float2 be2 = *(const float2*)(bet + d);
    float o0 = d0 * r * g2.x + be2.x;
    float o1 = d1 * r * g2.y + be2.y;
    *(float2*)(out + ro) = make_float2(o0, o1);
    *(uint32_t*)(oh + ro) = packh(o0, o1);
}

// ---------------- GEMM: pure fp16, 1 product ----------------------------------------
#define GSTG 3
#define GEMM_SMEM (GSTG*16384 + 1024)

__global__ __launch_bounds__(256, 2)
void gemm_mma(const __half* __restrict__ A, const __half* __restrict__ B,
              const float* __restrict__ bias,
              float* __restrict__ C, float* __restrict__ C2, float* __restrict__ C3,
              __half* __restrict__ Ch,
              int N, int K, int lda, int mode)
{
    extern __shared__ char dsm[];
    uint32_t raw = smem_u32(dsm);
    uint32_t s0 = (raw + 1023) & ~1023u;

    int tid = threadIdx.x, wid = tid >> 5, lane = tid & 31;
    int wm = wid & 1, wn = wid >> 1;
    long mBase = (long)blockIdx.y * 128;
    long nBase = (long)blockIdx.x * 128;
    int kOff = blockIdx.z * K;

    float acc[4][4][4];
    #pragma unroll
    for (int i = 0; i < 4; i++)
        #pragma unroll
        for (int j = 0; j < 4; j++)
            #pragma unroll
            for (int q = 0; q < 4; q++) acc[i][j][q] = 0.f;

    int lrow = tid >> 1, lkc0 = (tid & 1) * 2;
    const __half* Ap = A + (size_t)(mBase + lrow) * lda + kOff;
    const __half* Bp = B + (size_t)(nBase + lrow) * lda + kOff;
    uint32_t sw0 = swz(lrow * 64 + lkc0 * 16);
    uint32_t sw1 = swz(lrow * 64 + (lkc0 + 1) * 16);
    const int nIt = K / 32;

    #pragma unroll 1
    for (int pf = 0; pf < 2; pf++) {
        uint32_t sb = s0 + pf * 16384;
        int k0 = pf * 32 + lkc0 * 8;
        cpa16(sb + sw0, Ap + k0);          cpa16(sb + sw1, Ap + k0 + 8);
        cpa16(sb + 8192 + sw0, Bp + k0);   cpa16(sb + 8192 + sw1, Bp + k0 + 8);
        cp_commit();
    }

    #pragma unroll 1
    for (int it = 0; it < nIt; ++it) {
        if (it < nIt - 1) cp_wait<1>(); else cp_wait<0>();
        __syncthreads();
        if (it + 2 < nIt) {
            uint32_t sb = s0 + ((it + 2) % GSTG) * 16384;
            int k0 = (it + 2) * 32 + lkc0 * 8;
            cpa16(sb + sw0, Ap + k0);          cpa16(sb + sw1, Ap + k0 + 8);
            cpa16(sb + 8192 + sw0, Bp + k0);   cpa16(sb + 8192 + sw1, Bp + k0 + 8);
            cp_commit();
        }
        uint32_t base = s0 + (it % GSTG) * 16384;
        #pragma unroll
        for (int ks = 0; ks < 2; ks++) {
            uint32_t kcol = (ks * 2 + (lane >> 4)) * 16;
            int brow = wn * 32 + (lane & 15);
            uint32_t bfr[4][2];
            #pragma unroll
            for (int n2 = 0; n2 < 2; n2++) {
                uint32_t r0, r1, r2, r3;
                ldsm4(r0, r1, r2, r3, base + 8192 + swz((brow + n2 * 16) * 64 + kcol));
                bfr[n2*2][0] = r0; bfr[n2*2][1] = r2; bfr[n2*2+1][0] = r1; bfr[n2*2+1][1] = r3;
            }
            int arow = wm * 64 + (lane & 15);
            #pragma unroll
            for (int mt = 0; mt < 4; mt++) {
                uint32_t a[4];
                ldsm4(a[0], a[1], a[2], a[3], base + swz((arow + mt * 16) * 64 + kcol));
                #pragma unroll
                for (int nt = 0; nt < 4; nt++) mma_f16(acc[mt][nt], a, bfr[nt]);
            }
        }
    }

    float* dst = (blockIdx.z == 0) ? C : (blockIdx.z == 1 ? C2 : C3);
    #pragma unroll
    for (int mt = 0; mt < 4; mt++) {
        #pragma unroll
        for (int h2 = 0; h2 < 2; h2++) {
            long m = mBase + wm * 64 + mt * 16 + (lane >> 2) + h2 * 8;
            #pragma unroll
            for (int nt = 0; nt < 4; nt++) {
                long n0 = nBase + wn * 32 + nt * 8 + (lane & 3) * 2;
                float v0 = acc[mt][nt][h2 * 2];
                float v1 = acc[mt][nt][h2 * 2 + 1];
                if (mode == 0) {
                    *(float2*)(dst + m * N + n0) = make_float2(v0, v1);
                } else if (mode == 1) {
                    v0 += __ldg(bias + n0); v1 += __ldg(bias + n0 + 1);
                    v0 = 0.5f * v0 * (1.0f + erff(v0 * 0.70710678118654752f));
                    v1 = 0.5f * v1 * (1.0f + erff(v1 * 0.70710678118654752f));
                    *(uint32_t*)(Ch + m * N + n0) = packh(v0, v1);
                } else {
                    v0 += __ldg(bias + n0); v1 += __ldg(bias + n0 + 1);
                    float sc = (n0 < DD) ? 0.125f : 1.0f;
                    *(uint32_t*)(Ch + m * N + n0) = packh(v0 * sc, v1 * sc);
                }
            }
        }
    }
}

// ---------------- flash attention: all single fp16 ----------------------------------
#define A_QH 0
#define A_KV 16384               // stage s: 16KB (K 8KB + V 8KB)
#define A_MK (16384 + 49152)
#define ATTN_SMEM (65536 + 2048 + 1024)

__global__ __launch_bounds__(256, 1)
void attn_flash(const __half* __restrict__ qkv, const int* __restrict__ mask,
                __half* __restrict__ ctx16)
{
    extern __shared__ char dsm[];
    uint32_t raw = smem_u32(dsm);
    uint32_t s0 = (raw + 1023) & ~1023u;
    char* sm = dsm + (s0 - raw);

    int b = blockIdx.z, h = blockIdx.y, qt = blockIdx.x;
    int tid = threadIdx.x, wid = tid >> 5, lane = tid & 31;
    int q0 = b * SS + qt * 128;
    int k0g = b * SS;

    float* maskf = (float*)(sm + A_MK);
    for (int i = tid; i < SS; i += 256) maskf[i] = (float)mask[b * SS + i];

    #pragma unroll
    for (int r2 = 0; r2 < 4; r2++) {
        int i = tid + r2 * 256;
        int row = i >> 3, c = i & 7;
        uint32_t sw = swz(row * 128 + c * 16);
        cpa16(s0 + A_QH + sw, qkv + (size_t)(q0 + row) * NQKV + h * DH + c * 8);
    }
    cp_commit();

    // FIXED: cover all 64 rows (512 16B-chunks each for K and V)
    auto ldKV = [&](int ch, int stg) {
        uint32_t kb = s0 + A_KV + stg * 16384;
        #pragma unroll
        for (int r2 = 0; r2 < 2; r2++) {
            int i = tid + r2 * 256;
            int row = i >> 3, c = i & 7;
            uint32_t sw = swz(row * 128 + c * 16);
            size_t gk = (size_t)(k0g + ch * 64 + row) * NQKV + DD + h * DH + c * 8;
            cpa16(kb + sw,        qkv + gk);        // K
            cpa16(kb + 8192 + sw, qkv + gk + DD);   // V
        }
        cp_commit();
    };
    ldKV(0, 0);
    ldKV(1, 1);

    cp_wait<2>(); __syncthreads();

    uint32_t qh[4][4];
    {
        int qr = wid * 16 + (lane & 15);
        #pragma unroll
        for (int ks = 0; ks < 4; ks++) {
            uint32_t o2 = swz(qr * 128 + (ks * 2 + (lane >> 4)) * 16);
            ldsm4(qh[ks][0], qh[ks][1], qh[ks][2], qh[ks][3], s0 + A_QH + o2);
        }
    }

    float M[2] = {-1e30f, -1e30f}, Zs[2] = {0.f, 0.f}, Zm[2] = {0.f, 0.f};
    float o[8][4];
    #pragma unroll
    for (int i = 0; i < 8; i++)
        #pragma unroll
        for (int j = 0; j < 4; j++) o[i][j] = 0.f;

    #pragma unroll 1
    for (int ch = 0; ch < 8; ch++) {
        if (ch < 7) cp_wait<1>(); else cp_wait<0>();
        __syncthreads();
        if (ch + 2 < 8) ldKV(ch + 2, (ch + 2) % 3);

        uint32_t kb = s0 + A_KV + (ch % 3) * 16384;
        float s[8][4];
        #pragma unroll
        for (int i = 0; i < 8; i++)
            #pragma unroll
            for (int j = 0; j < 4; j++) s[i][j] = 0.f;

        #pragma unroll
        for (int n4 = 0; n4 < 4; n4++) {
            int br = n4 * 16 + (lane & 15);
            #pragma unroll
            for (int ks = 0; ks < 4; ks++) {
                uint32_t kcol = (ks * 2 + (lane >> 4)) * 16;
                uint32_t r0, r1, r2, r3;
                uint32_t b0[2], b1[2];
                ldsm4(r0, r1, r2, r3, kb + swz(br * 128 + kcol));
                b0[0] = r0; b0[1] = r2; b1[0] = r1; b1[1] = r3;
                mma_f16(s[n4*2], qh[ks], b0);  mma_f16(s[n4*2+1], qh[ks], b1);
            }
        }

        #pragma unroll
        for (int g = 0; g < 2; g++) {
            float mx = -1e30f;
            #pragma unroll
            for (int nt = 0; nt < 8; nt++)
                mx = fmaxf(mx, fmaxf(s[nt][2*g], s[nt][2*g+1]));
            mx = fmaxf(mx, __shfl_xor_sync(0xffffffffu, mx, 1));
            mx = fmaxf(mx, __shfl_xor_sync(0xffffffffu, mx, 2));
            float Mn = fmaxf(M[g], mx);
            float fac = __expf(M[g] - Mn);
            float zc = 0.f, zmc = 0.f;
            #pragma unroll
            for (int nt = 0; nt < 8; nt++) {
                #pragma unroll
                for (int e = 0; e < 2; e++) {
                    int col = ch * 64 + nt * 8 + (lane & 3) * 2 + e;
                    float ex = __expf(s[nt][2*g+e] - Mn);
                    float mm = maskf[col];
                    zc += ex; zmc += ex * mm;
                    s[nt][2*g+e] = ex * mm;
                }
            }
            zc += __shfl_xor_sync(0xffffffffu, zc, 1);
            zc += __shfl_xor_sync(0xffffffffu, zc, 2);
            zmc += __shfl_xor_sync(0xffffffffu, zmc, 1);
            zmc += __shfl_xor_sync(0xffffffffu, zmc, 2);
            Zs[g] = Zs[g] * fac + zc;
            Zm[g] = Zm[g] * fac + zmc;
            M[g] = Mn;
            #pragma unroll
            for (int nt = 0; nt < 8; nt++) { o[nt][2*g] *= fac; o[nt][2*g+1] *= fac; }
        }

        uint32_t ah[4][4];
        #pragma unroll
        for (int kt = 0; kt < 4; kt++) {
            ah[kt][0] = packh(s[2*kt][0],   s[2*kt][1]);
            ah[kt][1] = packh(s[2*kt][2],   s[2*kt][3]);
            ah[kt][2] = packh(s[2*kt+1][0], s[2*kt+1][1]);
            ah[kt][3] = packh(s[2*kt+1][2], s[2*kt+1][3]);
        }

        uint32_t vb = kb + 8192;
        #pragma unroll
        for (int n4 = 0; n4 < 4; n4++) {
            #pragma unroll
            for (int kt = 0; kt < 4; kt++) {
                uint32_t addr = swz((kt * 16 + (lane & 15)) * 128 + n4 * 32 + (lane >> 4) * 16);
                uint32_t r0, r1, r2, r3;
                uint32_t b0[2], b1[2];
                ldsm4t(r0, r1, r2, r3, vb + addr);
                b0[0] = r0; b0[1] = r1; b1[0] = r2; b1[1] = r3;
                mma_f16(o[n4*2], ah[kt], b0);  mma_f16(o[n4*2+1], ah[kt], b1);
            }
        }
    }

    #pragma unroll
    for (int g = 0; g < 2; g++) {
        float den = fmaxf(Zm[g], 1e-9f * Zs[g]);
        float rcp = 1.0f / den;
        size_t row = q0 + wid * 16 + (lane >> 2) + g * 8;
        #pragma unroll
        for (int nt = 0; nt < 8; nt++) {
            int col = h * DH + nt * 8 + (lane & 3) * 2;
            *(uint32_t*)(ctx16 + row * DD + col) = packh(o[nt][2*g] * rcp, o[nt][2*g+1] * rcp);
        }
    }
}

// ---------------- pool + normalize ------------------------------------------------
__global__ void pool_kernel(const float* __restrict__ h, const int* __restrict__ mask,
                            float* __restrict__ out)
{
    __shared__ float sent[DD];
    __shared__ float red[32];
    int b = blockIdx.x, tid = threadIdx.x;
    float ms = 0.f;
    for (int s = tid; s < SS; s += 256) ms += (float)mask[b * SS + s];
    ms = blockReduceSum(ms, red);
    float inv = 1.0f / fmaxf(ms, 1e-6f);
    for (int d = tid; d < DD; d += 256) {
        float a = 0.f;
        const float* hp = h + ((size_t)b * SS) * DD + d;
        const int* mp = mask + b * SS;
        for (int s = 0; s < SS; s++) a += hp[(size_t)s * DD] * (float)mp[s];
        sent[d] = a * inv;
    }
    __syncthreads();
    float sq = 0.f;
    for (int d = tid; d < DD; d += 256) sq += sent[d] * sent[d];
    sq = blockReduceSum(sq, red);
    float rn = 1.0f / fmaxf(sqrtf(sq), 1e-12f);
    for (int d = tid; d < DD; d += 256) out[b * DD + d] = sent[d] * rn;
}

// ---------------- launch -----------------------------------------------------------
extern "C" void kernel_launch(void* const* d_in, const int* in_sizes, int n_in,
                              void* d_out, int out_size)
{
    const int*   input_ids = (const int*)  d_in[0];
    const int*   amask     = (const int*)  d_in[1];
    const float* word_emb  = (const float*)d_in[2];
    const float* pos_emb   = (const float*)d_in[3];
    const float* type_emb  = (const float*)d_in[4];
    const float* emb_g     = (const float*)d_in[5];
    const float* emb_b     = (const float*)d_in[6];
    const float* Wq = (const float*)d_in[7];  const float* bq = (const float*)d_in[8];
    const float* Wk = (const float*)d_in[9];  const float* bk = (const float*)d_in[10];
    const float* Wv = (const float*)d_in[11]; const float* bv = (const float*)d_in[12];
    const float* Wo = (const float*)d_in[13]; const float* bo = (const float*)d_in[14];
    const float* ln1g = (const float*)d_in[15]; const float* ln1b = (const float*)d_in[16];
    const float* Wi = (const float*)d_in[17]; const float* bi = (const float*)d_in[18];
    const float* Wf = (const float*)d_in[19]; const float* bf = (const float*)d_in[20];
    const float* ln2g = (const float*)d_in[21]; const float* ln2b = (const float*)d_in[22];
    float* out = (float*)d_out;

    float *p_h, *p_t1, *p_t2, *p_t3, *p_bqkv;
    __half *p_h16, *p_qkv, *p_c16, *p_f16;
    __half *wqkv, *wo, *wi, *wf;
    cudaGetSymbolAddress((void**)&p_h,  g_h);
    cudaGetSymbolAddress((void**)&p_t1, g_t1);
    cudaGetSymbolAddress((void**)&p_t2, g_t2);
    cudaGetSymbolAddress((void**)&p_t3, g_t3);
    cudaGetSymbolAddress((void**)&p_bqkv, g_bqkv);
    cudaGetSymbolAddress((void**)&p_h16, g_h16);
    cudaGetSymbolAddress((void**)&p_qkv, g_qkv16);
    cudaGetSymbolAddress((void**)&p_c16, g_ctx16);
    cudaGetSymbolAddress((void**)&p_f16, g_ff16);
    cudaGetSymbolAddress((void**)&wqkv, g_Wqkv);
    cudaGetSymbolAddress((void**)&wo, g_WoT);
    cudaGetSymbolAddress((void**)&wi, g_WiT);
    cudaGetSymbolAddress((void**)&wf, g_WfT);

    cudaFuncSetAttribute(gemm_mma, cudaFuncAttributeMaxDynamicSharedMemorySize, GEMM_SMEM);
    cudaFuncSetAttribute(attn_flash, cudaFuncAttributeMaxDynamicSharedMemorySize, ATTN_SMEM);

    trans_all<<<LL * 6912, dim3(32, 8)>>>(Wq, Wk, Wv, Wo, Wi, Wf);
    fuse_bias<<<(LL * NQKV + 255) / 256, 256>>>(bq, bk, bv);
    embed_ln_kernel<<<MTOK, 384>>>(input_ids, word_emb, pos_emb, type_emb,
                                   emb_g, emb_b, p_h, p_h16);

    dim3 gQKV(NQKV / 128, MTOK / 128, 1);
    dim3 gSK3(DD   / 128, MTOK / 128, 3);
    dim3 gFF (FFD  / 128, MTOK / 128, 1);

    for (int l = 0; l < LL; l++) {
        size_t wdd = (size_t)l * DD * DD;
        size_t wdf = (size_t)l * DD * FFD;
        size_t wqk = (size_t)l * NQKV * DD;

        gemm_mma<<<gQKV, 256, GEMM_SMEM>>>(p_h16, wqkv + wqk, p_bqkv + l * NQKV,
                                           nullptr, nullptr, nullptr, p_qkv,
                                           NQKV, DD, DD, 3);

        attn_flash<<<dim3(4, HH, BB), 256, ATTN_SMEM>>>(p_qkv, amask, p_c16);

        gemm_mma<<<gSK3, 256, GEMM_SMEM>>>(p_c16, wo + wdd, nullptr,
                                           p_t1, p_t2, p_t3, nullptr,
                                           DD, DD / 3, DD, 0);
        ln_sum3_kernel<<<MTOK, 384>>>(p_t1, p_t2, p_t3, bo + l * DD, p_h,
                                      ln1g + l * DD, ln1b + l * DD, p_h, p_h16);

        gemm_mma<<<gFF, 256, GEMM_SMEM>>>(p_h16, wi + wdf, bi + l * FFD,
                                          nullptr, nullptr, nullptr, p_f16,
                                          FFD, DD, DD, 1);

        gemm_mma<<<gSK3, 256, GEMM_SMEM>>>(p_f16, wf + wdf, nullptr,
                                           p_t1, p_t2, p_t3, nullptr,
                                           DD, FFD / 3, FFD, 0);
        ln_sum3_kernel<<<MTOK, 384>>>(p_t1, p_t2, p_t3, bf + l * DD, p_h,
                                      ln2g + l * DD, ln2b + l * DD, p_h, p_h16);
    }

    pool_kernel<<<BB, 256>>>(p_h, amask, out);
}